// round 1
// baseline (speedup 1.0000x reference)
#include <cuda_runtime.h>
#include <math.h>

#define B_    2
#define T_    2048
#define C_    1024
#define H_    16
#define D_    64
#define M_    (B_ * T_)      // 4096
#define QKVN  (3 * C_)       // 3072

// Scratch (allocation-free rule: __device__ globals)
__device__ float g_qkv[M_ * QKVN];   // 48 MB
__device__ float g_y[M_ * C_];       // 16 MB

// ---------------------------------------------------------------------------
// SGEMM with bias: Co[M,N] = A[M,K] @ Bw[K,N] + bias[N]
// 128x128 block tile, BK=8, 256 threads, 8x8 per thread, float4 I/O.
// M,N,K all multiples of 128/8 here (4096, 3072|1024, 1024).
// ---------------------------------------------------------------------------
__global__ __launch_bounds__(256) void sgemm_bias_kernel(
    const float* __restrict__ A, const float* __restrict__ Bw,
    const float* __restrict__ bias, float* __restrict__ Co,
    int M, int N, int K)
{
    __shared__ float As[8][128];
    __shared__ float Bs[8][128];

    const int tid = threadIdx.x;
    const int tx  = tid & 15;       // 0..15
    const int ty  = tid >> 4;       // 0..15
    const int brow = blockIdx.y * 128;
    const int bcol = blockIdx.x * 128;

    // Load mapping
    const int ar  = tid >> 1;            // 0..127 (A row within tile)
    const int ac4 = (tid & 1) * 4;       // 0 or 4 (A k offset)
    const int brr = tid >> 5;            // 0..7   (B k row within tile)
    const int bc4 = (tid & 31) * 4;      // 0..124 (B col offset)

    const float* Aptr = A  + (size_t)(brow + ar) * K + ac4;
    const float* Bptr = Bw + (size_t)brr * N + bcol + bc4;

    float acc[8][8];
    #pragma unroll
    for (int i = 0; i < 8; i++)
        #pragma unroll
        for (int j = 0; j < 8; j++) acc[i][j] = 0.f;

    for (int k0 = 0; k0 < K; k0 += 8) {
        float4 av = *(const float4*)(Aptr + k0);
        float4 bv = *(const float4*)(Bptr + (size_t)k0 * N);
        As[ac4 + 0][ar] = av.x;
        As[ac4 + 1][ar] = av.y;
        As[ac4 + 2][ar] = av.z;
        As[ac4 + 3][ar] = av.w;
        *(float4*)&Bs[brr][bc4] = bv;
        __syncthreads();

        #pragma unroll
        for (int k = 0; k < 8; k++) {
            float af[8], bf[8];
            *(float4*)&af[0] = *(const float4*)&As[k][ty * 8];
            *(float4*)&af[4] = *(const float4*)&As[k][ty * 8 + 4];
            *(float4*)&bf[0] = *(const float4*)&Bs[k][tx * 8];
            *(float4*)&bf[4] = *(const float4*)&Bs[k][tx * 8 + 4];
            #pragma unroll
            for (int i = 0; i < 8; i++)
                #pragma unroll
                for (int j = 0; j < 8; j++)
                    acc[i][j] += af[i] * bf[j];
        }
        __syncthreads();
    }

    float4 bia0 = *(const float4*)(bias + bcol + tx * 8);
    float4 bia1 = *(const float4*)(bias + bcol + tx * 8 + 4);
    #pragma unroll
    for (int i = 0; i < 8; i++) {
        const size_t r = (size_t)(brow + ty * 8 + i);
        float4 o0 = make_float4(acc[i][0] + bia0.x, acc[i][1] + bia0.y,
                                acc[i][2] + bia0.z, acc[i][3] + bia0.w);
        float4 o1 = make_float4(acc[i][4] + bia1.x, acc[i][5] + bia1.y,
                                acc[i][6] + bia1.z, acc[i][7] + bia1.w);
        *(float4*)(Co + r * N + bcol + tx * 8)     = o0;
        *(float4*)(Co + r * N + bcol + tx * 8 + 4) = o1;
    }
}

// ---------------------------------------------------------------------------
// Flash attention (causal), fp32.
// Block = one (b,h, 64-query tile). 256 threads = 16x16; thread owns a 4x4
// patch of the 64x64 S-tile (and of the 64x64 O accumulator, D=64).
// K is staged d-major in smem (conflict-free float4 reads); V reuses the same
// buffer token-major. P goes through smem for the PV mini-GEMM.
// smem = 3 * 64 * 68 floats = 52224 B (dynamic).
// ---------------------------------------------------------------------------
#define STR 68
#define ATTN_SMEM (3 * 64 * STR * (int)sizeof(float))

__global__ __launch_bounds__(256) void attn_kernel(
    const float* __restrict__ qkv, float* __restrict__ y)
{
    extern __shared__ float sm[];
    float* Qs = sm;                 // [64][STR]  (pre-scaled Q, token-major)
    float* Xs = sm + 64 * STR;      // K d-major during S, then V token-major
    float* Ps = sm + 2 * 64 * STR;  // [64][STR]  P tile

    const int tid = threadIdx.x;
    const int tx  = tid & 15;
    const int ty  = tid >> 4;
    const int qtile = blockIdx.x;
    const int bh    = blockIdx.y;
    const int b = bh >> 4;
    const int h = bh & 15;

    const float* Qb = qkv + (size_t)b * T_ * QKVN + h * D_;
    const float* Kb = Qb + C_;
    const float* Vb = Qb + 2 * C_;
    const float scale = 0.125f;  // 1/sqrt(64)

    // Load Q tile (scaled). 4096 floats / 256 threads = 4 x float4 each.
    #pragma unroll
    for (int i = 0; i < 4; i++) {
        int f  = tid + i * 256;
        int r  = f >> 4;
        int c4 = (f & 15) * 4;
        float4 v = *(const float4*)(Qb + (size_t)(qtile * 64 + r) * QKVN + c4);
        v.x *= scale; v.y *= scale; v.z *= scale; v.w *= scale;
        *(float4*)&Qs[r * STR + c4] = v;
    }

    float mrow[4], lrow[4], o[4][4];
    #pragma unroll
    for (int i = 0; i < 4; i++) {
        mrow[i] = -1e30f; lrow[i] = 0.f;
        #pragma unroll
        for (int j = 0; j < 4; j++) o[i][j] = 0.f;
    }

    for (int kt = 0; kt <= qtile; kt++) {
        __syncthreads();
        // Load K tile TRANSPOSED: Xs[d][token]
        #pragma unroll
        for (int i = 0; i < 4; i++) {
            int f  = tid + i * 256;
            int r  = f >> 4;            // token
            int c4 = (f & 15) * 4;      // d
            float4 v = *(const float4*)(Kb + (size_t)(kt * 64 + r) * QKVN + c4);
            Xs[(c4 + 0) * STR + r] = v.x;
            Xs[(c4 + 1) * STR + r] = v.y;
            Xs[(c4 + 2) * STR + r] = v.z;
            Xs[(c4 + 3) * STR + r] = v.w;
        }
        __syncthreads();

        // S = Q @ K^T for this thread's 4x4 patch
        float s[4][4];
        #pragma unroll
        for (int i = 0; i < 4; i++)
            #pragma unroll
            for (int j = 0; j < 4; j++) s[i][j] = 0.f;

        #pragma unroll
        for (int d = 0; d < 64; d += 4) {
            float aq[4][4];
            #pragma unroll
            for (int i = 0; i < 4; i++)
                *(float4*)aq[i] = *(const float4*)&Qs[(ty * 4 + i) * STR + d];
            #pragma unroll
            for (int dd = 0; dd < 4; dd++) {
                float4 kv = *(const float4*)&Xs[(d + dd) * STR + tx * 4];
                #pragma unroll
                for (int i = 0; i < 4; i++) {
                    s[i][0] += aq[i][dd] * kv.x;
                    s[i][1] += aq[i][dd] * kv.y;
                    s[i][2] += aq[i][dd] * kv.z;
                    s[i][3] += aq[i][dd] * kv.w;
                }
            }
        }

        // Causal mask (diagonal tile only)
        if (kt == qtile) {
            #pragma unroll
            for (int i = 0; i < 4; i++) {
                int qi = ty * 4 + i;
                #pragma unroll
                for (int j = 0; j < 4; j++)
                    if (tx * 4 + j > qi) s[i][j] = -1e30f;
            }
        }

        __syncthreads();   // everyone done reading K from Xs

        // Load V tile token-major into Xs (overwrites K)
        #pragma unroll
        for (int i = 0; i < 4; i++) {
            int f  = tid + i * 256;
            int r  = f >> 4;
            int c4 = (f & 15) * 4;
            float4 v = *(const float4*)(Vb + (size_t)(kt * 64 + r) * QKVN + c4);
            *(float4*)&Xs[r * STR + c4] = v;
        }

        // Online softmax (register + half-warp shuffles; lanes of same ty
        // occupy a 16-lane shfl segment)
        #pragma unroll
        for (int i = 0; i < 4; i++) {
            float mx = fmaxf(fmaxf(s[i][0], s[i][1]), fmaxf(s[i][2], s[i][3]));
            #pragma unroll
            for (int off = 8; off >= 1; off >>= 1)
                mx = fmaxf(mx, __shfl_xor_sync(0xffffffffu, mx, off, 16));
            float mn    = fmaxf(mrow[i], mx);
            float alpha = __expf(mrow[i] - mn);
            float rs = 0.f;
            #pragma unroll
            for (int j = 0; j < 4; j++) {
                float p = __expf(s[i][j] - mn);
                s[i][j] = p;
                rs += p;
            }
            #pragma unroll
            for (int off = 8; off >= 1; off >>= 1)
                rs += __shfl_xor_sync(0xffffffffu, rs, off, 16);
            lrow[i] = lrow[i] * alpha + rs;
            mrow[i] = mn;
            #pragma unroll
            for (int j = 0; j < 4; j++) o[i][j] *= alpha;
            *(float4*)&Ps[(ty * 4 + i) * STR + tx * 4] =
                make_float4(s[i][0], s[i][1], s[i][2], s[i][3]);
        }
        __syncthreads();   // Ps written, V loaded

        // O += P @ V
        #pragma unroll
        for (int j2 = 0; j2 < 64; j2 += 4) {
            float pp[4][4];
            #pragma unroll
            for (int i = 0; i < 4; i++)
                *(float4*)pp[i] = *(const float4*)&Ps[(ty * 4 + i) * STR + j2];
            #pragma unroll
            for (int jj = 0; jj < 4; jj++) {
                float4 vv = *(const float4*)&Xs[(j2 + jj) * STR + tx * 4];
                #pragma unroll
                for (int i = 0; i < 4; i++) {
                    o[i][0] += pp[i][jj] * vv.x;
                    o[i][1] += pp[i][jj] * vv.y;
                    o[i][2] += pp[i][jj] * vv.z;
                    o[i][3] += pp[i][jj] * vv.w;
                }
            }
        }
    }

    // Normalize and write y[B,T,C]
    #pragma unroll
    for (int i = 0; i < 4; i++) {
        float inv = 1.f / lrow[i];
        size_t r = (size_t)b * T_ + qtile * 64 + ty * 4 + i;
        float4 ov = make_float4(o[i][0] * inv, o[i][1] * inv,
                                o[i][2] * inv, o[i][3] * inv);
        *(float4*)(y + r * C_ + h * D_ + tx * 4) = ov;
    }
}

// ---------------------------------------------------------------------------
extern "C" void kernel_launch(void* const* d_in, const int* in_sizes, int n_in,
                              void* d_out, int out_size)
{
    const float* x     = (const float*)d_in[0];
    const float* Wqkv  = (const float*)d_in[1];
    const float* bqkv  = (const float*)d_in[2];
    const float* Wproj = (const float*)d_in[3];
    const float* bproj = (const float*)d_in[4];
    float* out = (float*)d_out;

    float* qkv_p = nullptr;
    float* y_p   = nullptr;
    cudaGetSymbolAddress((void**)&qkv_p, g_qkv);
    cudaGetSymbolAddress((void**)&y_p,   g_y);

    cudaFuncSetAttribute(attn_kernel,
                         cudaFuncAttributeMaxDynamicSharedMemorySize, ATTN_SMEM);

    // 1) QKV projection: [4096,1024] @ [1024,3072]
    sgemm_bias_kernel<<<dim3(QKVN / 128, M_ / 128), 256>>>(
        x, Wqkv, bqkv, qkv_p, M_, QKVN, C_);

    // 2) Causal flash attention
    attn_kernel<<<dim3(T_ / 64, B_ * H_), 256, ATTN_SMEM>>>(qkv_p, y_p);

    // 3) Output projection: [4096,1024] @ [1024,1024]
    sgemm_bias_kernel<<<dim3(C_ / 128, M_ / 128), 256>>>(
        y_p, Wproj, bproj, out, M_, C_, C_);
}

// round 3
// speedup vs baseline: 1.3133x; 1.3133x over previous
#include <cuda_runtime.h>
#include <cuda_bf16.h>
#include <cstdint>
#include <math.h>

#define B_    2
#define T_    2048
#define C_    1024
#define H_    16
#define D_    64
#define M_    4096
#define QKVN  3072
#define KB_   3072            // expanded bf16 K (3 * 1024)
#define NIT   (KB_ / 32)      // 96 k-iterations of BK=32

// ---- scratch (__device__ globals; no allocation allowed) -------------------
__device__ float g_qkv[M_ * QKVN];                 // 48 MB
__device__ float g_y[M_ * C_];                     // 16 MB
__device__ __nv_bfloat16 gA[M_ * KB_];             // 24 MB expanded activations
__device__ __nv_bfloat16 gBq[QKVN * (size_t)KB_];  // 18 MB W_qkv^T expanded
__device__ __nv_bfloat16 gBp[C_ * (size_t)KB_];    // 6 MB  W_proj^T expanded

// ============================================================================
// small PTX helpers (all <= compute_80 features)
// ============================================================================
__device__ __forceinline__ uint32_t smem_u32(const void* p) {
    uint32_t a;
    asm("{ .reg .u64 t; cvta.to.shared.u64 t, %1; cvt.u32.u64 %0, t; }" : "=r"(a) : "l"(p));
    return a;
}
__device__ __forceinline__ void cp16(uint32_t dst, const void* src) {
    asm volatile("cp.async.cg.shared.global [%0], [%1], 16;" :: "r"(dst), "l"(src));
}
#define CP_COMMIT() asm volatile("cp.async.commit_group;" ::: "memory")
#define CP_WAIT1()  asm volatile("cp.async.wait_group 1;" ::: "memory")

__device__ __forceinline__ void ldm4(uint32_t* r, uint32_t addr) {
    asm volatile("ldmatrix.sync.aligned.m8n8.x4.shared.b16 {%0,%1,%2,%3}, [%4];"
        : "=r"(r[0]), "=r"(r[1]), "=r"(r[2]), "=r"(r[3]) : "r"(addr));
}
__device__ __forceinline__ void mma16816(float* c, const uint32_t* a, const uint32_t* b) {
    asm volatile(
        "mma.sync.aligned.m16n8k16.row.col.f32.bf16.bf16.f32 "
        "{%0,%1,%2,%3}, {%4,%5,%6,%7}, {%8,%9}, {%0,%1,%2,%3};"
        : "+f"(c[0]), "+f"(c[1]), "+f"(c[2]), "+f"(c[3])
        : "r"(a[0]), "r"(a[1]), "r"(a[2]), "r"(a[3]), "r"(b[0]), "r"(b[1]));
}

// ============================================================================
// Conversion kernels (fp32 -> error-compensated bf16 triplets)
// A side: per k -> [hi, hi, lo];  B side: per k -> [hi, lo, hi]
// ============================================================================
__global__ __launch_bounds__(256) void convert_act(const float* __restrict__ x,
                                                   __nv_bfloat16* __restrict__ A) {
    int idx = blockIdx.x * 256 + threadIdx.x;          // M_ * (C_/8) threads
    int m  = idx >> 7;
    int kg = idx & 127;
    const float* p = x + (size_t)m * C_ + kg * 8;
    float4 v0 = *(const float4*)p;
    float4 v1 = *(const float4*)(p + 4);
    float v[8] = {v0.x, v0.y, v0.z, v0.w, v1.x, v1.y, v1.z, v1.w};
    union { __nv_bfloat16 h[24]; uint4 u[3]; } o;
    #pragma unroll
    for (int j = 0; j < 8; j++) {
        __nv_bfloat16 hi = __float2bfloat16(v[j]);
        __nv_bfloat16 lo = __float2bfloat16(v[j] - __bfloat162float(hi));
        o.h[3*j + 0] = hi; o.h[3*j + 1] = hi; o.h[3*j + 2] = lo;
    }
    uint4* dst = (uint4*)(A + (size_t)m * KB_ + kg * 24);
    dst[0] = o.u[0]; dst[1] = o.u[1]; dst[2] = o.u[2];
}

// W[K][N] fp32 -> Wp[N][3K] bf16 (transposed + expanded)
__global__ __launch_bounds__(128) void convert_w(const float* __restrict__ W,
                                                 __nv_bfloat16* __restrict__ Wp, int N) {
    __shared__ float s[32][33];
    int n0 = blockIdx.x * 32, k0 = blockIdx.y * 32;
    int t = threadIdx.x;
    {
        int kr = t >> 3, nc = (t & 7) * 4;
        #pragma unroll
        for (int i = 0; i < 2; i++) {
            int k = kr + i * 16;
            float4 v = *(const float4*)(W + (size_t)(k0 + k) * N + n0 + nc);
            s[k][nc] = v.x; s[k][nc+1] = v.y; s[k][nc+2] = v.z; s[k][nc+3] = v.w;
        }
    }
    __syncthreads();
    int nl = t >> 2, kg = t & 3;
    union { __nv_bfloat16 h[24]; uint4 u[3]; } o;
    #pragma unroll
    for (int j = 0; j < 8; j++) {
        float v = s[kg * 8 + j][nl];
        __nv_bfloat16 hi = __float2bfloat16(v);
        __nv_bfloat16 lo = __float2bfloat16(v - __bfloat162float(hi));
        o.h[3*j + 0] = hi; o.h[3*j + 1] = lo; o.h[3*j + 2] = hi;
    }
    uint4* dst = (uint4*)(Wp + (size_t)(n0 + nl) * KB_ + (size_t)(k0 + kg * 8) * 3);
    dst[0] = o.u[0]; dst[1] = o.u[1]; dst[2] = o.u[2];
}

// ============================================================================
// HMMA GEMM: Co[M_,Ntot] = A'[M_,KB_](bf16) @ B'[Ntot,KB_](bf16)^T + bias
// CTA 128x128, 8 warps (2x4), warp tile 64x32, BK=32, 3-stage cp.async.
// smem rows padded to 80B -> conflict-free ldmatrix & cp.async stores.
// ============================================================================
#define TSTR   80                      // bytes per smem row (32 bf16 + pad)
#define TILEB  (128 * TSTR)            // 10240 B per operand tile
#define STAGEB (2 * TILEB)             // A + B per stage
#define GSMEM  (3 * STAGEB)            // 61440 B

__global__ __launch_bounds__(256, 1) void gemm_tc(
    const __nv_bfloat16* __restrict__ A, const __nv_bfloat16* __restrict__ Bw,
    const float* __restrict__ bias, float* __restrict__ Co, int Ntot)
{
    extern __shared__ char smemraw[];
    const uint32_t sb = smem_u32(smemraw);

    const int tid  = threadIdx.x;
    const int lane = tid & 31;
    const int wid  = tid >> 5;
    const int wr   = wid >> 2;      // 0..1  (warp row -> 64 rows)
    const int wc   = wid & 3;       // 0..3  (warp col -> 32 cols)
    const int brow = blockIdx.y * 128;
    const int bcol = blockIdx.x * 128;

    const __nv_bfloat16* Ag = A  + (size_t)brow * KB_;
    const __nv_bfloat16* Bg = Bw + (size_t)bcol * KB_;

    // per-thread cp.async coordinates: chunk c = tid + 256*i; row=c>>2, ch=c&3
    const int r0l = tid >> 2, ch0 = tid & 3;

    float acc[4][4][4];
    #pragma unroll
    for (int mt = 0; mt < 4; mt++)
        #pragma unroll
        for (int nt = 0; nt < 4; nt++)
            #pragma unroll
            for (int q = 0; q < 4; q++) acc[mt][nt][q] = 0.f;

    // ldmatrix source addresses (within a stage buffer)
    const int arow = (lane & 7) + ((lane >> 3) & 1) * 8;
    const int achk = lane >> 4;
    const int brw  = (lane & 7) + ((lane >> 4) & 1) * 8;
    const int bchk = (lane >> 3) & 1;
    const uint32_t aoff = (uint32_t)((wr * 64 + arow) * TSTR + achk * 16);
    const uint32_t boff = (uint32_t)(TILEB + (wc * 32 + brw) * TSTR + bchk * 16);

    // ---- load helper (macro-free lambda) ----
    auto load_stage = [&](int s, int buf) {
        const uint32_t base = sb + (uint32_t)buf * STAGEB;
        #pragma unroll
        for (int i = 0; i < 2; i++) {
            int row = r0l + i * 64;
            int ch  = ch0;
            cp16(base + (uint32_t)(row * TSTR + ch * 16),
                 Ag + (size_t)row * KB_ + s * 32 + ch * 8);
            cp16(base + (uint32_t)(TILEB + row * TSTR + ch * 16),
                 Bg + (size_t)row * KB_ + s * 32 + ch * 8);
        }
    };

    load_stage(0, 0); CP_COMMIT();
    load_stage(1, 1); CP_COMMIT();

    int buf = 0;
    #pragma unroll 1
    for (int s = 0; s < NIT; s++) {
        CP_WAIT1();
        __syncthreads();

        if (s + 2 < NIT) load_stage(s + 2, (s + 2) % 3);
        CP_COMMIT();

        const uint32_t base = sb + (uint32_t)buf * STAGEB;
        #pragma unroll
        for (int ks = 0; ks < 2; ks++) {
            uint32_t afr[4][4], bfr[2][4];
            #pragma unroll
            for (int mt = 0; mt < 4; mt++)
                ldm4(afr[mt], base + aoff + (uint32_t)(mt * 16 * TSTR + ks * 32));
            #pragma unroll
            for (int bt = 0; bt < 2; bt++)
                ldm4(bfr[bt], base + boff + (uint32_t)(bt * 16 * TSTR + ks * 32));
            #pragma unroll
            for (int mt = 0; mt < 4; mt++)
                #pragma unroll
                for (int nt = 0; nt < 4; nt++)
                    mma16816(acc[mt][nt], afr[mt], &bfr[nt >> 1][(nt & 1) * 2]);
        }
        buf++; if (buf == 3) buf = 0;
    }

    // ---- epilogue: direct float2 stores + bias ----
    const int crow = lane >> 2;
    const int ccol = (lane & 3) * 2;
    #pragma unroll
    for (int nt = 0; nt < 4; nt++) {
        int col = bcol + wc * 32 + nt * 8 + ccol;
        float2 bi = *(const float2*)(bias + col);
        #pragma unroll
        for (int mt = 0; mt < 4; mt++) {
            int row = brow + wr * 64 + mt * 16 + crow;
            float2 v0 = make_float2(acc[mt][nt][0] + bi.x, acc[mt][nt][1] + bi.y);
            float2 v1 = make_float2(acc[mt][nt][2] + bi.x, acc[mt][nt][3] + bi.y);
            *(float2*)(Co + (size_t)row * Ntot + col)       = v0;
            *(float2*)(Co + (size_t)(row + 8) * Ntot + col) = v1;
        }
    }
}

// ============================================================================
// Flash attention (causal), fp32 — unchanged from R1
// ============================================================================
#define STR 68
#define ATTN_SMEM (3 * 64 * STR * (int)sizeof(float))

__global__ __launch_bounds__(256) void attn_kernel(
    const float* __restrict__ qkv, float* __restrict__ y)
{
    extern __shared__ float sm[];
    float* Qs = sm;
    float* Xs = sm + 64 * STR;
    float* Ps = sm + 2 * 64 * STR;

    const int tid = threadIdx.x;
    const int tx  = tid & 15;
    const int ty  = tid >> 4;
    const int qtile = blockIdx.x;
    const int bh    = blockIdx.y;
    const int b = bh >> 4;
    const int h = bh & 15;

    const float* Qb = qkv + (size_t)b * T_ * QKVN + h * D_;
    const float* Kb = Qb + C_;
    const float* Vb = Qb + 2 * C_;
    const float scale = 0.125f;

    #pragma unroll
    for (int i = 0; i < 4; i++) {
        int f  = tid + i * 256;
        int r  = f >> 4;
        int c4 = (f & 15) * 4;
        float4 v = *(const float4*)(Qb + (size_t)(qtile * 64 + r) * QKVN + c4);
        v.x *= scale; v.y *= scale; v.z *= scale; v.w *= scale;
        *(float4*)&Qs[r * STR + c4] = v;
    }

    float mrow[4], lrow[4], o[4][4];
    #pragma unroll
    for (int i = 0; i < 4; i++) {
        mrow[i] = -1e30f; lrow[i] = 0.f;
        #pragma unroll
        for (int j = 0; j < 4; j++) o[i][j] = 0.f;
    }

    for (int kt = 0; kt <= qtile; kt++) {
        __syncthreads();
        #pragma unroll
        for (int i = 0; i < 4; i++) {
            int f  = tid + i * 256;
            int r  = f >> 4;
            int c4 = (f & 15) * 4;
            float4 v = *(const float4*)(Kb + (size_t)(kt * 64 + r) * QKVN + c4);
            Xs[(c4 + 0) * STR + r] = v.x;
            Xs[(c4 + 1) * STR + r] = v.y;
            Xs[(c4 + 2) * STR + r] = v.z;
            Xs[(c4 + 3) * STR + r] = v.w;
        }
        __syncthreads();

        float s[4][4];
        #pragma unroll
        for (int i = 0; i < 4; i++)
            #pragma unroll
            for (int j = 0; j < 4; j++) s[i][j] = 0.f;

        #pragma unroll
        for (int d = 0; d < 64; d += 4) {
            float aq[4][4];
            #pragma unroll
            for (int i = 0; i < 4; i++)
                *(float4*)aq[i] = *(const float4*)&Qs[(ty * 4 + i) * STR + d];
            #pragma unroll
            for (int dd = 0; dd < 4; dd++) {
                float4 kv = *(const float4*)&Xs[(d + dd) * STR + tx * 4];
                #pragma unroll
                for (int i = 0; i < 4; i++) {
                    s[i][0] += aq[i][dd] * kv.x;
                    s[i][1] += aq[i][dd] * kv.y;
                    s[i][2] += aq[i][dd] * kv.z;
                    s[i][3] += aq[i][dd] * kv.w;
                }
            }
        }

        if (kt == qtile) {
            #pragma unroll
            for (int i = 0; i < 4; i++) {
                int qi = ty * 4 + i;
                #pragma unroll
                for (int j = 0; j < 4; j++)
                    if (tx * 4 + j > qi) s[i][j] = -1e30f;
            }
        }

        __syncthreads();

        #pragma unroll
        for (int i = 0; i < 4; i++) {
            int f  = tid + i * 256;
            int r  = f >> 4;
            int c4 = (f & 15) * 4;
            float4 v = *(const float4*)(Vb + (size_t)(kt * 64 + r) * QKVN + c4);
            *(float4*)&Xs[r * STR + c4] = v;
        }

        #pragma unroll
        for (int i = 0; i < 4; i++) {
            float mx = fmaxf(fmaxf(s[i][0], s[i][1]), fmaxf(s[i][2], s[i][3]));
            #pragma unroll
            for (int off = 8; off >= 1; off >>= 1)
                mx = fmaxf(mx, __shfl_xor_sync(0xffffffffu, mx, off, 16));
            float mn    = fmaxf(mrow[i], mx);
            float alpha = __expf(mrow[i] - mn);
            float rs = 0.f;
            #pragma unroll
            for (int j = 0; j < 4; j++) {
                float p = __expf(s[i][j] - mn);
                s[i][j] = p;
                rs += p;
            }
            #pragma unroll
            for (int off = 8; off >= 1; off >>= 1)
                rs += __shfl_xor_sync(0xffffffffu, rs, off, 16);
            lrow[i] = lrow[i] * alpha + rs;
            mrow[i] = mn;
            #pragma unroll
            for (int j = 0; j < 4; j++) o[i][j] *= alpha;
            *(float4*)&Ps[(ty * 4 + i) * STR + tx * 4] =
                make_float4(s[i][0], s[i][1], s[i][2], s[i][3]);
        }
        __syncthreads();

        #pragma unroll
        for (int j2 = 0; j2 < 64; j2 += 4) {
            float pp[4][4];
            #pragma unroll
            for (int i = 0; i < 4; i++)
                *(float4*)pp[i] = *(const float4*)&Ps[(ty * 4 + i) * STR + j2];
            #pragma unroll
            for (int jj = 0; jj < 4; jj++) {
                float4 vv = *(const float4*)&Xs[(j2 + jj) * STR + tx * 4];
                #pragma unroll
                for (int i = 0; i < 4; i++) {
                    o[i][0] += pp[i][jj] * vv.x;
                    o[i][1] += pp[i][jj] * vv.y;
                    o[i][2] += pp[i][jj] * vv.z;
                    o[i][3] += pp[i][jj] * vv.w;
                }
            }
        }
    }

    #pragma unroll
    for (int i = 0; i < 4; i++) {
        float inv = 1.f / lrow[i];
        size_t r = (size_t)b * T_ + qtile * 64 + ty * 4 + i;
        float4 ov = make_float4(o[i][0] * inv, o[i][1] * inv,
                                o[i][2] * inv, o[i][3] * inv);
        *(float4*)(y + r * C_ + h * D_ + tx * 4) = ov;
    }
}

// ---------------------------------------------------------------------------
extern "C" void kernel_launch(void* const* d_in, const int* in_sizes, int n_in,
                              void* d_out, int out_size)
{
    const float* x     = (const float*)d_in[0];
    const float* Wqkv  = (const float*)d_in[1];
    const float* bqkv  = (const float*)d_in[2];
    const float* Wproj = (const float*)d_in[3];
    const float* bproj = (const float*)d_in[4];
    float* out = (float*)d_out;

    float *qkv_p = nullptr, *y_p = nullptr;
    __nv_bfloat16 *gA_p = nullptr, *gBq_p = nullptr, *gBp_p = nullptr;
    cudaGetSymbolAddress((void**)&qkv_p, g_qkv);
    cudaGetSymbolAddress((void**)&y_p,   g_y);
    cudaGetSymbolAddress((void**)&gA_p,  gA);
    cudaGetSymbolAddress((void**)&gBq_p, gBq);
    cudaGetSymbolAddress((void**)&gBp_p, gBp);

    cudaFuncSetAttribute(attn_kernel,
                         cudaFuncAttributeMaxDynamicSharedMemorySize, ATTN_SMEM);
    cudaFuncSetAttribute(gemm_tc,
                         cudaFuncAttributeMaxDynamicSharedMemorySize, GSMEM);

    // conversions
    convert_w<<<dim3(QKVN / 32, C_ / 32), 128>>>(Wqkv, gBq_p, QKVN);
    convert_w<<<dim3(C_ / 32, C_ / 32), 128>>>(Wproj, gBp_p, C_);
    convert_act<<<(M_ * C_ / 8) / 256, 256>>>(x, gA_p);

    // 1) QKV projection
    gemm_tc<<<dim3(QKVN / 128, M_ / 128), 256, GSMEM>>>(
        gA_p, gBq_p, bqkv, qkv_p, QKVN);

    // 2) causal flash attention
    attn_kernel<<<dim3(T_ / 64, B_ * H_), 256, ATTN_SMEM>>>(qkv_p, y_p);

    // 3) output projection
    convert_act<<<(M_ * C_ / 8) / 256, 256>>>(y_p, gA_p);
    gemm_tc<<<dim3(C_ / 128, M_ / 128), 256, GSMEM>>>(
        gA_p, gBp_p, bproj, out, C_);
}

// round 5
// speedup vs baseline: 2.0596x; 1.5683x over previous
#include <cuda_runtime.h>
#include <cuda_bf16.h>
#include <cstdint>
#include <math.h>

#define B_    2
#define T_    2048
#define C_    1024
#define H_    16
#define D_    64
#define M_    4096
#define QKVN  3072
#define KB_   3072            // expanded bf16 K (3 * 1024)
#define NIT   (KB_ / 32)      // 96 k-iterations of BK=32

// ---- scratch (__device__ globals; no allocation allowed) -------------------
__device__ float g_qkv[M_ * QKVN];                 // 48 MB
__device__ float g_y[M_ * C_];                     // 16 MB
__device__ __nv_bfloat16 gA[M_ * KB_];             // 24 MB expanded activations
__device__ __nv_bfloat16 gBq[QKVN * (size_t)KB_];  // 18 MB W_qkv^T expanded
__device__ __nv_bfloat16 gBp[C_ * (size_t)KB_];    // 6 MB  W_proj^T expanded

// ============================================================================
// small PTX helpers (all <= compute_80 features)
// ============================================================================
__device__ __forceinline__ uint32_t smem_u32(const void* p) {
    uint32_t a;
    asm("{ .reg .u64 t; cvta.to.shared.u64 t, %1; cvt.u32.u64 %0, t; }" : "=r"(a) : "l"(p));
    return a;
}
__device__ __forceinline__ void cp16(uint32_t dst, const void* src) {
    asm volatile("cp.async.cg.shared.global [%0], [%1], 16;" :: "r"(dst), "l"(src));
}
#define CP_COMMIT() asm volatile("cp.async.commit_group;" ::: "memory")
#define CP_WAIT1()  asm volatile("cp.async.wait_group 1;" ::: "memory")

__device__ __forceinline__ void ldm4(uint32_t* r, uint32_t addr) {
    asm volatile("ldmatrix.sync.aligned.m8n8.x4.shared.b16 {%0,%1,%2,%3}, [%4];"
        : "=r"(r[0]), "=r"(r[1]), "=r"(r[2]), "=r"(r[3]) : "r"(addr));
}
__device__ __forceinline__ void mma16816(float* c, const uint32_t* a, const uint32_t* b) {
    asm volatile(
        "mma.sync.aligned.m16n8k16.row.col.f32.bf16.bf16.f32 "
        "{%0,%1,%2,%3}, {%4,%5,%6,%7}, {%8,%9}, {%0,%1,%2,%3};"
        : "+f"(c[0]), "+f"(c[1]), "+f"(c[2]), "+f"(c[3])
        : "r"(a[0]), "r"(a[1]), "r"(a[2]), "r"(a[3]), "r"(b[0]), "r"(b[1]));
}
__device__ __forceinline__ uint32_t pack_bf2(__nv_bfloat16 lo, __nv_bfloat16 hi) {
    return ((uint32_t)__bfloat16_as_ushort(hi) << 16) | (uint32_t)__bfloat16_as_ushort(lo);
}

// ============================================================================
// Conversion kernels (fp32 -> error-compensated bf16 triplets) for GEMMs
// A side: per k -> [hi, hi, lo];  B side: per k -> [hi, lo, hi]
// ============================================================================
__global__ __launch_bounds__(256) void convert_act(const float* __restrict__ x,
                                                   __nv_bfloat16* __restrict__ A) {
    int idx = blockIdx.x * 256 + threadIdx.x;
    int m  = idx >> 7;
    int kg = idx & 127;
    const float* p = x + (size_t)m * C_ + kg * 8;
    float4 v0 = *(const float4*)p;
    float4 v1 = *(const float4*)(p + 4);
    float v[8] = {v0.x, v0.y, v0.z, v0.w, v1.x, v1.y, v1.z, v1.w};
    union { __nv_bfloat16 h[24]; uint4 u[3]; } o;
    #pragma unroll
    for (int j = 0; j < 8; j++) {
        __nv_bfloat16 hi = __float2bfloat16(v[j]);
        __nv_bfloat16 lo = __float2bfloat16(v[j] - __bfloat162float(hi));
        o.h[3*j + 0] = hi; o.h[3*j + 1] = hi; o.h[3*j + 2] = lo;
    }
    uint4* dst = (uint4*)(A + (size_t)m * KB_ + kg * 24);
    dst[0] = o.u[0]; dst[1] = o.u[1]; dst[2] = o.u[2];
}

__global__ __launch_bounds__(128) void convert_w(const float* __restrict__ W,
                                                 __nv_bfloat16* __restrict__ Wp, int N) {
    __shared__ float s[32][33];
    int n0 = blockIdx.x * 32, k0 = blockIdx.y * 32;
    int t = threadIdx.x;
    {
        int kr = t >> 3, nc = (t & 7) * 4;
        #pragma unroll
        for (int i = 0; i < 2; i++) {
            int k = kr + i * 16;
            float4 v = *(const float4*)(W + (size_t)(k0 + k) * N + n0 + nc);
            s[k][nc] = v.x; s[k][nc+1] = v.y; s[k][nc+2] = v.z; s[k][nc+3] = v.w;
        }
    }
    __syncthreads();
    int nl = t >> 2, kg = t & 3;
    union { __nv_bfloat16 h[24]; uint4 u[3]; } o;
    #pragma unroll
    for (int j = 0; j < 8; j++) {
        float v = s[kg * 8 + j][nl];
        __nv_bfloat16 hi = __float2bfloat16(v);
        __nv_bfloat16 lo = __float2bfloat16(v - __bfloat162float(hi));
        o.h[3*j + 0] = hi; o.h[3*j + 1] = lo; o.h[3*j + 2] = hi;
    }
    uint4* dst = (uint4*)(Wp + (size_t)(n0 + nl) * KB_ + (size_t)(k0 + kg * 8) * 3);
    dst[0] = o.u[0]; dst[1] = o.u[1]; dst[2] = o.u[2];
}

// ============================================================================
// HMMA GEMM (2 CTAs/SM)
// ============================================================================
#define TSTR   80
#define TILEB  (128 * TSTR)
#define STAGEB (2 * TILEB)
#define GSMEM  (3 * STAGEB)

__global__ __launch_bounds__(256, 2) void gemm_tc(
    const __nv_bfloat16* __restrict__ A, const __nv_bfloat16* __restrict__ Bw,
    const float* __restrict__ bias, float* __restrict__ Co, int Ntot)
{
    extern __shared__ char smemraw[];
    const uint32_t sb = smem_u32(smemraw);

    const int tid  = threadIdx.x;
    const int lane = tid & 31;
    const int wid  = tid >> 5;
    const int wr   = wid >> 2;
    const int wc   = wid & 3;
    const int brow = blockIdx.y * 128;
    const int bcol = blockIdx.x * 128;

    const __nv_bfloat16* Ag = A  + (size_t)brow * KB_;
    const __nv_bfloat16* Bg = Bw + (size_t)bcol * KB_;

    const int r0l = tid >> 2, ch0 = tid & 3;

    float acc[4][4][4];
    #pragma unroll
    for (int mt = 0; mt < 4; mt++)
        #pragma unroll
        for (int nt = 0; nt < 4; nt++)
            #pragma unroll
            for (int q = 0; q < 4; q++) acc[mt][nt][q] = 0.f;

    const int arow = (lane & 7) + ((lane >> 3) & 1) * 8;
    const int achk = lane >> 4;
    const int brw  = (lane & 7) + ((lane >> 4) & 1) * 8;
    const int bchk = (lane >> 3) & 1;
    const uint32_t aoff = (uint32_t)((wr * 64 + arow) * TSTR + achk * 16);
    const uint32_t boff = (uint32_t)(TILEB + (wc * 32 + brw) * TSTR + bchk * 16);

    auto load_stage = [&](int s, int buf) {
        const uint32_t base = sb + (uint32_t)buf * STAGEB;
        #pragma unroll
        for (int i = 0; i < 2; i++) {
            int row = r0l + i * 64;
            int ch  = ch0;
            cp16(base + (uint32_t)(row * TSTR + ch * 16),
                 Ag + (size_t)row * KB_ + s * 32 + ch * 8);
            cp16(base + (uint32_t)(TILEB + row * TSTR + ch * 16),
                 Bg + (size_t)row * KB_ + s * 32 + ch * 8);
        }
    };

    load_stage(0, 0); CP_COMMIT();
    load_stage(1, 1); CP_COMMIT();

    int buf = 0;
    #pragma unroll 1
    for (int s = 0; s < NIT; s++) {
        CP_WAIT1();
        __syncthreads();

        if (s + 2 < NIT) load_stage(s + 2, (s + 2) % 3);
        CP_COMMIT();

        const uint32_t base = sb + (uint32_t)buf * STAGEB;
        #pragma unroll
        for (int ks = 0; ks < 2; ks++) {
            uint32_t afr[4][4], bfr[2][4];
            #pragma unroll
            for (int mt = 0; mt < 4; mt++)
                ldm4(afr[mt], base + aoff + (uint32_t)(mt * 16 * TSTR + ks * 32));
            #pragma unroll
            for (int bt = 0; bt < 2; bt++)
                ldm4(bfr[bt], base + boff + (uint32_t)(bt * 16 * TSTR + ks * 32));
            #pragma unroll
            for (int mt = 0; mt < 4; mt++)
                #pragma unroll
                for (int nt = 0; nt < 4; nt++)
                    mma16816(acc[mt][nt], afr[mt], &bfr[nt >> 1][(nt & 1) * 2]);
        }
        buf++; if (buf == 3) buf = 0;
    }

    const int crow = lane >> 2;
    const int ccol = (lane & 3) * 2;
    #pragma unroll
    for (int nt = 0; nt < 4; nt++) {
        int col = bcol + wc * 32 + nt * 8 + ccol;
        float2 bi = *(const float2*)(bias + col);
        #pragma unroll
        for (int mt = 0; mt < 4; mt++) {
            int row = brow + wr * 64 + mt * 16 + crow;
            float2 v0 = make_float2(acc[mt][nt][0] + bi.x, acc[mt][nt][1] + bi.y);
            float2 v1 = make_float2(acc[mt][nt][2] + bi.x, acc[mt][nt][3] + bi.y);
            *(float2*)(Co + (size_t)row * Ntot + col)       = v0;
            *(float2*)(Co + (size_t)(row + 8) * Ntot + col) = v1;
        }
    }
}

// ============================================================================
// HMMA flash attention (causal), error-compensated bf16.
// CTA: 64 queries, 4 warps (warp = 16 query rows x full 64-key / 64-d width).
// Rows hold [hi(64) | lo(64)] bf16; 3 mma passes: (hi,hi), (hi,lo), (lo,hi).
// ============================================================================
#define ASTR 272
#define ATTN_SMEM (4 * 64 * ASTR)   // Qs, Ks, Vs, Ps = 69632 B

__global__ __launch_bounds__(128, 3) void attn_mma(
    const float* __restrict__ qkv, float* __restrict__ y)
{
    extern __shared__ char smbuf[];
    char* Qs = smbuf;
    char* Ks = Qs + 64 * ASTR;
    char* Vs = Ks + 64 * ASTR;
    char* Ps = Vs + 64 * ASTR;
    const uint32_t qs_b = smem_u32(Qs);
    const uint32_t ks_b = qs_b + 64 * ASTR;
    const uint32_t vs_b = ks_b + 64 * ASTR;
    const uint32_t ps_b = vs_b + 64 * ASTR;

    const int tid  = threadIdx.x;
    const int lane = tid & 31;
    const int wid  = tid >> 5;
    const int qt   = (int)gridDim.x - 1 - (int)blockIdx.x;   // long CTAs first
    const int bh   = blockIdx.y;
    const int b = bh >> 4, h = bh & 15;

    const float* Qb = qkv + (size_t)b * T_ * QKVN + h * D_;
    const float* Kb = Qb + C_;
    const float* Vb = Qb + 2 * C_;

    // ldmatrix lane maps (proven in gemm_tc)
    const int arow = (lane & 7) + ((lane >> 3) & 1) * 8;
    const int achk = lane >> 4;
    const int brw  = (lane & 7) + ((lane >> 4) & 1) * 8;
    const int bchk = (lane >> 3) & 1;
    const uint32_t aoff = (uint32_t)((wid * 16 + arow) * ASTR + achk * 16);
    uint32_t boffs[4];
    #pragma unroll
    for (int n2 = 0; n2 < 4; n2++)
        boffs[n2] = (uint32_t)((n2 * 16 + brw) * ASTR + bchk * 16);

    // ---- stage Q (scale 0.125, hi/lo split). thread: row=tid>>1, dhalf
    {
        int r = tid >> 1, d0 = (tid & 1) * 32;
        const float* src = Qb + (size_t)(qt * 64 + r) * QKVN + d0;
        union { __nv_bfloat16 h[32]; uint4 u[4]; } Hh, Ll;
        #pragma unroll
        for (int i = 0; i < 32; i += 4) {
            float4 v = *(const float4*)(src + i);
            float vv[4] = {v.x, v.y, v.z, v.w};
            #pragma unroll
            for (int j = 0; j < 4; j++) {
                float f = vv[j] * 0.125f;
                __nv_bfloat16 hi = __float2bfloat16(f);
                Hh.h[i + j] = hi;
                Ll.h[i + j] = __float2bfloat16(f - __bfloat162float(hi));
            }
        }
        char* row = Qs + r * ASTR;
        #pragma unroll
        for (int i = 0; i < 4; i++) {
            *(uint4*)(row + 2 * d0 + 16 * i)       = Hh.u[i];
            *(uint4*)(row + 128 + 2 * d0 + 16 * i) = Ll.u[i];
        }
    }

    float m0 = -1e30f, m1 = -1e30f, l0 = 0.f, l1 = 0.f;
    float accO[8][4];
    #pragma unroll
    for (int nt = 0; nt < 8; nt++)
        #pragma unroll
        for (int q = 0; q < 4; q++) accO[nt][q] = 0.f;

    const int r0 = lane >> 2;        // warp-local rows: r0, r0+8 (of 16)
    const int c0 = (lane & 3) * 2;   // base col within n8 tile
    const int row0 = wid * 16 + r0;  // tile-local row (for causal mask)

    // 3-pass (hi,hi),(hi,lo),(lo,hi) mma over one 64-wide contraction
    auto gemm3 = [&](float (&acc)[8][4], uint32_t abase, uint32_t bbase) {
        #pragma unroll
        for (int pass = 0; pass < 3; pass++) {
            uint32_t aadd = (pass == 2) ? 128u : 0u;
            uint32_t badd = (pass == 1) ? 128u : 0u;
            #pragma unroll
            for (int ks = 0; ks < 4; ks++) {
                uint32_t afr[4], bfr[4][4];
                ldm4(afr, abase + aoff + aadd + ks * 32);
                #pragma unroll
                for (int n2 = 0; n2 < 4; n2++)
                    ldm4(bfr[n2], bbase + boffs[n2] + badd + ks * 32);
                #pragma unroll
                for (int nt = 0; nt < 8; nt++)
                    mma16816(acc[nt], afr, &bfr[nt >> 1][(nt & 1) * 2]);
            }
        }
    };

    #pragma unroll 1
    for (int kt = 0; kt <= qt; kt++) {
        __syncthreads();   // prev PV done: Ks/Vs/Ps free

        // ---- stage K (hi/lo split): thread row=tid>>1, dhalf
        {
            int r = tid >> 1, d0 = (tid & 1) * 32;
            const float* src = Kb + (size_t)(kt * 64 + r) * QKVN + d0;
            union { __nv_bfloat16 h[32]; uint4 u[4]; } Hh, Ll;
            #pragma unroll
            for (int i = 0; i < 32; i += 4) {
                float4 v = *(const float4*)(src + i);
                float vv[4] = {v.x, v.y, v.z, v.w};
                #pragma unroll
                for (int j = 0; j < 4; j++) {
                    __nv_bfloat16 hi = __float2bfloat16(vv[j]);
                    Hh.h[i + j] = hi;
                    Ll.h[i + j] = __float2bfloat16(vv[j] - __bfloat162float(hi));
                }
            }
            char* row = Ks + r * ASTR;
            #pragma unroll
            for (int i = 0; i < 4; i++) {
                *(uint4*)(row + 2 * d0 + 16 * i)       = Hh.u[i];
                *(uint4*)(row + 128 + 2 * d0 + 16 * i) = Ll.u[i];
            }
        }
        // ---- stage V transposed (hi/lo): thread d=tid>>1, keyhalf
        {
            int d = tid >> 1, k0 = (tid & 1) * 32;
            const float* src = Vb + (size_t)(kt * 64 + k0) * QKVN + d;
            union { __nv_bfloat16 h[32]; uint4 u[4]; } Hh, Ll;
            #pragma unroll
            for (int i = 0; i < 32; i++) {
                float f = src[(size_t)i * QKVN];
                __nv_bfloat16 hi = __float2bfloat16(f);
                Hh.h[i] = hi;
                Ll.h[i] = __float2bfloat16(f - __bfloat162float(hi));
            }
            char* row = Vs + d * ASTR;
            #pragma unroll
            for (int i = 0; i < 4; i++) {
                *(uint4*)(row + 2 * k0 + 16 * i)       = Hh.u[i];
                *(uint4*)(row + 128 + 2 * k0 + 16 * i) = Ll.u[i];
            }
        }
        __syncthreads();   // Ks, Vs ready

        // ---- S = Q @ K^T (3-pass compensated)
        float accS[8][4];
        #pragma unroll
        for (int nt = 0; nt < 8; nt++)
            #pragma unroll
            for (int q = 0; q < 4; q++) accS[nt][q] = 0.f;
        gemm3(accS, qs_b, ks_b);

        // ---- causal mask on diagonal tile (tile-local row = wid*16 + r0!)
        if (kt == qt) {
            #pragma unroll
            for (int nt = 0; nt < 8; nt++) {
                int col = nt * 8 + c0;
                if (col     > row0)     accS[nt][0] = -1e30f;
                if (col + 1 > row0)     accS[nt][1] = -1e30f;
                if (col     > row0 + 8) accS[nt][2] = -1e30f;
                if (col + 1 > row0 + 8) accS[nt][3] = -1e30f;
            }
        }

        // ---- online softmax + write P (hi/lo blocks)
        {
            float mx0 = -1e30f, mx1 = -1e30f;
            #pragma unroll
            for (int nt = 0; nt < 8; nt++) {
                mx0 = fmaxf(mx0, fmaxf(accS[nt][0], accS[nt][1]));
                mx1 = fmaxf(mx1, fmaxf(accS[nt][2], accS[nt][3]));
            }
            mx0 = fmaxf(mx0, __shfl_xor_sync(0xffffffffu, mx0, 1));
            mx0 = fmaxf(mx0, __shfl_xor_sync(0xffffffffu, mx0, 2));
            mx1 = fmaxf(mx1, __shfl_xor_sync(0xffffffffu, mx1, 1));
            mx1 = fmaxf(mx1, __shfl_xor_sync(0xffffffffu, mx1, 2));

            float mn0 = fmaxf(m0, mx0), mn1 = fmaxf(m1, mx1);
            float al0 = __expf(m0 - mn0), al1 = __expf(m1 - mn1);
            m0 = mn0; m1 = mn1;

            char* prow0 = Ps + (wid * 16 + r0) * ASTR + c0 * 2;
            char* prow1 = prow0 + 8 * ASTR;
            float sum0 = 0.f, sum1 = 0.f;
            #pragma unroll
            for (int nt = 0; nt < 8; nt++) {
                float p0 = __expf(accS[nt][0] - mn0);
                float p1 = __expf(accS[nt][1] - mn0);
                float p2 = __expf(accS[nt][2] - mn1);
                float p3 = __expf(accS[nt][3] - mn1);
                sum0 += p0 + p1; sum1 += p2 + p3;
                __nv_bfloat16 h0 = __float2bfloat16(p0), h1 = __float2bfloat16(p1);
                __nv_bfloat16 h2 = __float2bfloat16(p2), h3 = __float2bfloat16(p3);
                __nv_bfloat16 g0 = __float2bfloat16(p0 - __bfloat162float(h0));
                __nv_bfloat16 g1 = __float2bfloat16(p1 - __bfloat162float(h1));
                __nv_bfloat16 g2 = __float2bfloat16(p2 - __bfloat162float(h2));
                __nv_bfloat16 g3 = __float2bfloat16(p3 - __bfloat162float(h3));
                *(uint32_t*)(prow0 + nt * 16)        = pack_bf2(h0, h1);
                *(uint32_t*)(prow0 + 128 + nt * 16)  = pack_bf2(g0, g1);
                *(uint32_t*)(prow1 + nt * 16)        = pack_bf2(h2, h3);
                *(uint32_t*)(prow1 + 128 + nt * 16)  = pack_bf2(g2, g3);
            }
            sum0 += __shfl_xor_sync(0xffffffffu, sum0, 1);
            sum0 += __shfl_xor_sync(0xffffffffu, sum0, 2);
            sum1 += __shfl_xor_sync(0xffffffffu, sum1, 1);
            sum1 += __shfl_xor_sync(0xffffffffu, sum1, 2);
            l0 = l0 * al0 + sum0;
            l1 = l1 * al1 + sum1;

            #pragma unroll
            for (int nt = 0; nt < 8; nt++) {
                accO[nt][0] *= al0; accO[nt][1] *= al0;
                accO[nt][2] *= al1; accO[nt][3] *= al1;
            }
        }
        __syncthreads();   // Ps ready

        // ---- O += P @ V (3-pass compensated)
        gemm3(accO, ps_b, vs_b);
    }

    // ---- normalize + store
    float inv0 = 1.f / l0, inv1 = 1.f / l1;
    int grow = qt * 64 + wid * 16 + r0;
    float* y0 = y + ((size_t)b * T_ + grow) * C_ + h * D_;
    float* y1 = y0 + 8 * C_;
    #pragma unroll
    for (int nt = 0; nt < 8; nt++) {
        int d = nt * 8 + c0;
        *(float2*)(y0 + d) = make_float2(accO[nt][0] * inv0, accO[nt][1] * inv0);
        *(float2*)(y1 + d) = make_float2(accO[nt][2] * inv1, accO[nt][3] * inv1);
    }
}

// ---------------------------------------------------------------------------
extern "C" void kernel_launch(void* const* d_in, const int* in_sizes, int n_in,
                              void* d_out, int out_size)
{
    const float* x     = (const float*)d_in[0];
    const float* Wqkv  = (const float*)d_in[1];
    const float* bqkv  = (const float*)d_in[2];
    const float* Wproj = (const float*)d_in[3];
    const float* bproj = (const float*)d_in[4];
    float* out = (float*)d_out;

    float *qkv_p = nullptr, *y_p = nullptr;
    __nv_bfloat16 *gA_p = nullptr, *gBq_p = nullptr, *gBp_p = nullptr;
    cudaGetSymbolAddress((void**)&qkv_p, g_qkv);
    cudaGetSymbolAddress((void**)&y_p,   g_y);
    cudaGetSymbolAddress((void**)&gA_p,  gA);
    cudaGetSymbolAddress((void**)&gBq_p, gBq);
    cudaGetSymbolAddress((void**)&gBp_p, gBp);

    cudaFuncSetAttribute(attn_mma,
                         cudaFuncAttributeMaxDynamicSharedMemorySize, ATTN_SMEM);
    cudaFuncSetAttribute(gemm_tc,
                         cudaFuncAttributeMaxDynamicSharedMemorySize, GSMEM);

    // conversions
    convert_w<<<dim3(QKVN / 32, C_ / 32), 128>>>(Wqkv, gBq_p, QKVN);
    convert_w<<<dim3(C_ / 32, C_ / 32), 128>>>(Wproj, gBp_p, C_);
    convert_act<<<(M_ * C_ / 8) / 256, 256>>>(x, gA_p);

    // 1) QKV projection
    gemm_tc<<<dim3(QKVN / 128, M_ / 128), 256, GSMEM>>>(
        gA_p, gBq_p, bqkv, qkv_p, QKVN);

    // 2) causal flash attention (tensor cores)
    attn_mma<<<dim3(T_ / 64, B_ * H_), 128, ATTN_SMEM>>>(qkv_p, y_p);

    // 3) output projection
    convert_act<<<(M_ * C_ / 8) / 256, 256>>>(y_p, gA_p);
    gemm_tc<<<dim3(C_ / 128, M_ / 128), 256, GSMEM>>>(
        gA_p, gBp_p, bproj, out, C_);
}

// round 6
// speedup vs baseline: 2.3146x; 1.1238x over previous
#include <cuda_runtime.h>
#include <cuda_bf16.h>
#include <cstdint>
#include <math.h>

#define B_    2
#define T_    2048
#define C_    1024
#define H_    16
#define D_    64
#define M_    4096
#define QKVN  3072
#define KB_   3072            // expanded bf16 K (3 * 1024)
#define NIT   (KB_ / 32)      // 96 k-iterations of BK=32

// ---- scratch (__device__ globals; no allocation allowed) -------------------
__device__ float g_qkv[M_ * QKVN];                 // 48 MB
__device__ float g_y[M_ * C_];                     // 16 MB
__device__ __nv_bfloat16 gA[M_ * KB_];             // 24 MB expanded activations
__device__ __nv_bfloat16 gBq[QKVN * (size_t)KB_];  // 18 MB W_qkv^T expanded
__device__ __nv_bfloat16 gBp[C_ * (size_t)KB_];    // 6 MB  W_proj^T expanded
// per-(b,h) hi/lo split q,k,v: [bh][T][128] ([hi(64)|lo(64)] per token row)
__device__ __nv_bfloat16 gQsp[B_ * H_ * T_ * 128];
__device__ __nv_bfloat16 gKsp[B_ * H_ * T_ * 128];
__device__ __nv_bfloat16 gVsp[B_ * H_ * T_ * 128];

// ============================================================================
// small PTX helpers (all <= compute_80 features)
// ============================================================================
__device__ __forceinline__ uint32_t smem_u32(const void* p) {
    uint32_t a;
    asm("{ .reg .u64 t; cvta.to.shared.u64 t, %1; cvt.u32.u64 %0, t; }" : "=r"(a) : "l"(p));
    return a;
}
__device__ __forceinline__ void cp16(uint32_t dst, const void* src) {
    asm volatile("cp.async.cg.shared.global [%0], [%1], 16;" :: "r"(dst), "l"(src));
}
#define CP_COMMIT() asm volatile("cp.async.commit_group;" ::: "memory")
#define CP_WAIT1()  asm volatile("cp.async.wait_group 1;" ::: "memory")
#define CP_WAIT0()  asm volatile("cp.async.wait_group 0;" ::: "memory")

__device__ __forceinline__ void ldm4(uint32_t* r, uint32_t addr) {
    asm volatile("ldmatrix.sync.aligned.m8n8.x4.shared.b16 {%0,%1,%2,%3}, [%4];"
        : "=r"(r[0]), "=r"(r[1]), "=r"(r[2]), "=r"(r[3]) : "r"(addr));
}
__device__ __forceinline__ void ldm4t(uint32_t* r, uint32_t addr) {
    asm volatile("ldmatrix.sync.aligned.m8n8.x4.trans.shared.b16 {%0,%1,%2,%3}, [%4];"
        : "=r"(r[0]), "=r"(r[1]), "=r"(r[2]), "=r"(r[3]) : "r"(addr));
}
__device__ __forceinline__ void mma16816(float* c, const uint32_t* a, const uint32_t* b) {
    asm volatile(
        "mma.sync.aligned.m16n8k16.row.col.f32.bf16.bf16.f32 "
        "{%0,%1,%2,%3}, {%4,%5,%6,%7}, {%8,%9}, {%0,%1,%2,%3};"
        : "+f"(c[0]), "+f"(c[1]), "+f"(c[2]), "+f"(c[3])
        : "r"(a[0]), "r"(a[1]), "r"(a[2]), "r"(a[3]), "r"(b[0]), "r"(b[1]));
}
__device__ __forceinline__ uint32_t pack_bf2(__nv_bfloat16 lo, __nv_bfloat16 hi) {
    return ((uint32_t)__bfloat16_as_ushort(hi) << 16) | (uint32_t)__bfloat16_as_ushort(lo);
}

// ============================================================================
// Conversion kernels
// ============================================================================
// fp32 -> interleaved bf16 triplets for GEMM A-side: [hi, hi, lo]
__global__ __launch_bounds__(256) void convert_act(const float* __restrict__ x,
                                                   __nv_bfloat16* __restrict__ A) {
    int idx = blockIdx.x * 256 + threadIdx.x;
    int m  = idx >> 7;
    int kg = idx & 127;
    const float* p = x + (size_t)m * C_ + kg * 8;
    float4 v0 = *(const float4*)p;
    float4 v1 = *(const float4*)(p + 4);
    float v[8] = {v0.x, v0.y, v0.z, v0.w, v1.x, v1.y, v1.z, v1.w};
    union { __nv_bfloat16 h[24]; uint4 u[3]; } o;
    #pragma unroll
    for (int j = 0; j < 8; j++) {
        __nv_bfloat16 hi = __float2bfloat16(v[j]);
        __nv_bfloat16 lo = __float2bfloat16(v[j] - __bfloat162float(hi));
        o.h[3*j + 0] = hi; o.h[3*j + 1] = hi; o.h[3*j + 2] = lo;
    }
    uint4* dst = (uint4*)(A + (size_t)m * KB_ + kg * 24);
    dst[0] = o.u[0]; dst[1] = o.u[1]; dst[2] = o.u[2];
}

// W[K][N] fp32 -> Wp[N][3K] bf16 (transposed + expanded): [hi, lo, hi]
__global__ __launch_bounds__(128) void convert_w(const float* __restrict__ W,
                                                 __nv_bfloat16* __restrict__ Wp, int N) {
    __shared__ float s[32][33];
    int n0 = blockIdx.x * 32, k0 = blockIdx.y * 32;
    int t = threadIdx.x;
    {
        int kr = t >> 3, nc = (t & 7) * 4;
        #pragma unroll
        for (int i = 0; i < 2; i++) {
            int k = kr + i * 16;
            float4 v = *(const float4*)(W + (size_t)(k0 + k) * N + n0 + nc);
            s[k][nc] = v.x; s[k][nc+1] = v.y; s[k][nc+2] = v.z; s[k][nc+3] = v.w;
        }
    }
    __syncthreads();
    int nl = t >> 2, kg = t & 3;
    union { __nv_bfloat16 h[24]; uint4 u[3]; } o;
    #pragma unroll
    for (int j = 0; j < 8; j++) {
        float v = s[kg * 8 + j][nl];
        __nv_bfloat16 hi = __float2bfloat16(v);
        __nv_bfloat16 lo = __float2bfloat16(v - __bfloat162float(hi));
        o.h[3*j + 0] = hi; o.h[3*j + 1] = lo; o.h[3*j + 2] = hi;
    }
    uint4* dst = (uint4*)(Wp + (size_t)(n0 + nl) * KB_ + (size_t)(k0 + kg * 8) * 3);
    dst[0] = o.u[0]; dst[1] = o.u[1]; dst[2] = o.u[2];
}

// fp32 qkv -> per-(b,h) hi/lo split arrays (Q pre-scaled by 1/8)
__global__ __launch_bounds__(256) void convert_qkv(const float* __restrict__ qkv,
                                                   __nv_bfloat16* __restrict__ Qs,
                                                   __nv_bfloat16* __restrict__ Ks,
                                                   __nv_bfloat16* __restrict__ Vs) {
    int i = blockIdx.x * 256 + threadIdx.x;   // M_ * 384 total
    int m   = i / 384;
    int j   = i - m * 384;
    int p   = j >> 7;          // 0=q,1=k,2=v
    int rem = j & 127;
    int h   = rem >> 3;
    int d8  = (rem & 7) * 8;
    const float* src = qkv + (size_t)m * QKVN + p * C_ + h * D_ + d8;
    float4 v0 = *(const float4*)src;
    float4 v1 = *(const float4*)(src + 4);
    float sc = (p == 0) ? 0.125f : 1.0f;
    float v[8] = {v0.x, v0.y, v0.z, v0.w, v1.x, v1.y, v1.z, v1.w};
    union { __nv_bfloat16 h[8]; uint4 u; } Hh, Ll;
    #pragma unroll
    for (int q = 0; q < 8; q++) {
        float f = v[q] * sc;
        __nv_bfloat16 hi = __float2bfloat16(f);
        Hh.h[q] = hi;
        Ll.h[q] = __float2bfloat16(f - __bfloat162float(hi));
    }
    int b = m >> 11, t = m & 2047;
    __nv_bfloat16* base = (p == 0) ? Qs : (p == 1) ? Ks : Vs;
    __nv_bfloat16* dst = base + (((size_t)(b * H_ + h) * T_) + t) * 128 + d8;
    *(uint4*)dst        = Hh.u;
    *(uint4*)(dst + 64) = Ll.u;
}

// ============================================================================
// HMMA GEMM (unchanged from R5; 2 CTAs/SM)
// ============================================================================
#define TSTR   80
#define TILEB  (128 * TSTR)
#define STAGEB (2 * TILEB)
#define GSMEM  (3 * STAGEB)

__global__ __launch_bounds__(256, 2) void gemm_tc(
    const __nv_bfloat16* __restrict__ A, const __nv_bfloat16* __restrict__ Bw,
    const float* __restrict__ bias, float* __restrict__ Co, int Ntot)
{
    extern __shared__ char smemraw[];
    const uint32_t sb = smem_u32(smemraw);

    const int tid  = threadIdx.x;
    const int lane = tid & 31;
    const int wid  = tid >> 5;
    const int wr   = wid >> 2;
    const int wc   = wid & 3;
    const int brow = blockIdx.y * 128;
    const int bcol = blockIdx.x * 128;

    const __nv_bfloat16* Ag = A  + (size_t)brow * KB_;
    const __nv_bfloat16* Bg = Bw + (size_t)bcol * KB_;

    const int r0l = tid >> 2, ch0 = tid & 3;

    float acc[4][4][4];
    #pragma unroll
    for (int mt = 0; mt < 4; mt++)
        #pragma unroll
        for (int nt = 0; nt < 4; nt++)
            #pragma unroll
            for (int q = 0; q < 4; q++) acc[mt][nt][q] = 0.f;

    const int arow = (lane & 7) + ((lane >> 3) & 1) * 8;
    const int achk = lane >> 4;
    const int brw  = (lane & 7) + ((lane >> 4) & 1) * 8;
    const int bchk = (lane >> 3) & 1;
    const uint32_t aoff = (uint32_t)((wr * 64 + arow) * TSTR + achk * 16);
    const uint32_t boff = (uint32_t)(TILEB + (wc * 32 + brw) * TSTR + bchk * 16);

    auto load_stage = [&](int s, int buf) {
        const uint32_t base = sb + (uint32_t)buf * STAGEB;
        #pragma unroll
        for (int i = 0; i < 2; i++) {
            int row = r0l + i * 64;
            int ch  = ch0;
            cp16(base + (uint32_t)(row * TSTR + ch * 16),
                 Ag + (size_t)row * KB_ + s * 32 + ch * 8);
            cp16(base + (uint32_t)(TILEB + row * TSTR + ch * 16),
                 Bg + (size_t)row * KB_ + s * 32 + ch * 8);
        }
    };

    load_stage(0, 0); CP_COMMIT();
    load_stage(1, 1); CP_COMMIT();

    int buf = 0;
    #pragma unroll 1
    for (int s = 0; s < NIT; s++) {
        CP_WAIT1();
        __syncthreads();

        if (s + 2 < NIT) load_stage(s + 2, (s + 2) % 3);
        CP_COMMIT();

        const uint32_t base = sb + (uint32_t)buf * STAGEB;
        #pragma unroll
        for (int ks = 0; ks < 2; ks++) {
            uint32_t afr[4][4], bfr[2][4];
            #pragma unroll
            for (int mt = 0; mt < 4; mt++)
                ldm4(afr[mt], base + aoff + (uint32_t)(mt * 16 * TSTR + ks * 32));
            #pragma unroll
            for (int bt = 0; bt < 2; bt++)
                ldm4(bfr[bt], base + boff + (uint32_t)(bt * 16 * TSTR + ks * 32));
            #pragma unroll
            for (int mt = 0; mt < 4; mt++)
                #pragma unroll
                for (int nt = 0; nt < 4; nt++)
                    mma16816(acc[mt][nt], afr[mt], &bfr[nt >> 1][(nt & 1) * 2]);
        }
        buf++; if (buf == 3) buf = 0;
    }

    const int crow = lane >> 2;
    const int ccol = (lane & 3) * 2;
    #pragma unroll
    for (int nt = 0; nt < 4; nt++) {
        int col = bcol + wc * 32 + nt * 8 + ccol;
        float2 bi = *(const float2*)(bias + col);
        #pragma unroll
        for (int mt = 0; mt < 4; mt++) {
            int row = brow + wr * 64 + mt * 16 + crow;
            float2 v0 = make_float2(acc[mt][nt][0] + bi.x, acc[mt][nt][1] + bi.y);
            float2 v1 = make_float2(acc[mt][nt][2] + bi.x, acc[mt][nt][3] + bi.y);
            *(float2*)(Co + (size_t)row * Ntot + col)       = v0;
            *(float2*)(Co + (size_t)(row + 8) * Ntot + col) = v1;
        }
    }
}

// ============================================================================
// HMMA flash attention v2: pre-split inputs, cp.async double-buffered K/V,
// V consumed via ldmatrix.trans. CTA = 64 queries x 4 warps, 2 CTAs/SM.
// smem: Q | K0 | V0 | K1 | V1 | P, each 64 rows x 272B ([hi|lo] + 16B pad).
// ============================================================================
#define ASTR  272
#define ATILE (64 * ASTR)
#define ATTN_SMEM (6 * ATILE)   // 104448 B

__global__ __launch_bounds__(128, 2) void attn_mma(
    const __nv_bfloat16* __restrict__ Qsp, const __nv_bfloat16* __restrict__ Ksp,
    const __nv_bfloat16* __restrict__ Vsp, float* __restrict__ y)
{
    extern __shared__ char smbuf[];
    const uint32_t sb   = smem_u32(smbuf);
    const uint32_t qs_b = sb;
    const uint32_t ps_b = sb + 5 * ATILE;
    char* Psc = smbuf + 5 * ATILE;

    const int tid  = threadIdx.x;
    const int lane = tid & 31;
    const int wid  = tid >> 5;
    const int qt   = (int)gridDim.x - 1 - (int)blockIdx.x;   // long CTAs first
    const int bh   = blockIdx.y;
    const int b = bh >> 4, h = bh & 15;

    const __nv_bfloat16* Qg = Qsp + ((size_t)bh * T_ + qt * 64) * 128;
    const __nv_bfloat16* Kg = Ksp + (size_t)bh * T_ * 128;
    const __nv_bfloat16* Vg = Vsp + (size_t)bh * T_ * 128;

    // stage one 64x256B tile (16B chunks, coalesced)
    auto stage64 = [&](uint32_t sm, const __nv_bfloat16* g) {
        const char* gc = (const char*)g;
        #pragma unroll
        for (int i = 0; i < 8; i++) {
            int c = tid + 128 * i;
            cp16(sm + (uint32_t)((c >> 4) * ASTR + (c & 15) * 16),
                 gc + (c >> 4) * 256 + (c & 15) * 16);
        }
    };

    // fragment lane maps
    const int arow = (lane & 7) + ((lane >> 3) & 1) * 8;
    const int achk = lane >> 4;
    const uint32_t aoff = (uint32_t)((wid * 16 + arow) * ASTR + achk * 16);
    const int brw  = (lane & 7) + ((lane >> 4) & 1) * 8;
    const int bchk = (lane >> 3) & 1;
    uint32_t boffs[4];
    #pragma unroll
    for (int n2 = 0; n2 < 4; n2++)
        boffs[n2] = (uint32_t)((n2 * 16 + brw) * ASTR + bchk * 16);
    // V (row-major tokens) consumed via ldmatrix.trans: A-style lane map
    const uint32_t voff = (uint32_t)(arow * ASTR + achk * 16);

    // prologue: Q + tile 0 of K,V into buffer 0
    stage64(qs_b, Qg);
    stage64(sb + 1 * ATILE, Kg);
    stage64(sb + 2 * ATILE, Vg);
    CP_COMMIT();

    float m0 = -1e30f, m1 = -1e30f, l0 = 0.f, l1 = 0.f;
    float accO[8][4];
    #pragma unroll
    for (int nt = 0; nt < 8; nt++)
        #pragma unroll
        for (int q = 0; q < 4; q++) accO[nt][q] = 0.f;

    const int r0 = lane >> 2;
    const int c0 = (lane & 3) * 2;
    const int row0 = wid * 16 + r0;

    #pragma unroll 1
    for (int kt = 0; kt <= qt; kt++) {
        CP_WAIT0();
        __syncthreads();
        const uint32_t kbuf = sb + (uint32_t)(1 + 2 * (kt & 1)) * ATILE;
        const uint32_t vbuf = kbuf + ATILE;

        // prefetch next tile into the other buffer
        if (kt < qt) {
            uint32_t nb = sb + (uint32_t)(1 + 2 * ((kt + 1) & 1)) * ATILE;
            stage64(nb,         Kg + (size_t)(kt + 1) * 64 * 128);
            stage64(nb + ATILE, Vg + (size_t)(kt + 1) * 64 * 128);
        }
        CP_COMMIT();

        // ---- S = Q @ K^T (3-pass: hi*hi, hi*lo, lo*hi)
        float accS[8][4];
        #pragma unroll
        for (int nt = 0; nt < 8; nt++)
            #pragma unroll
            for (int q = 0; q < 4; q++) accS[nt][q] = 0.f;
        #pragma unroll
        for (int pass = 0; pass < 3; pass++) {
            uint32_t aadd = (pass == 2) ? 128u : 0u;
            uint32_t badd = (pass == 1) ? 128u : 0u;
            #pragma unroll
            for (int ks = 0; ks < 4; ks++) {
                uint32_t afr[4], bfr[4][4];
                ldm4(afr, qs_b + aoff + aadd + ks * 32);
                #pragma unroll
                for (int n2 = 0; n2 < 4; n2++)
                    ldm4(bfr[n2], kbuf + boffs[n2] + badd + ks * 32);
                #pragma unroll
                for (int nt = 0; nt < 8; nt++)
                    mma16816(accS[nt], afr, &bfr[nt >> 1][(nt & 1) * 2]);
            }
        }

        // ---- causal mask on diagonal tile
        if (kt == qt) {
            #pragma unroll
            for (int nt = 0; nt < 8; nt++) {
                int col = nt * 8 + c0;
                if (col     > row0)     accS[nt][0] = -1e30f;
                if (col + 1 > row0)     accS[nt][1] = -1e30f;
                if (col     > row0 + 8) accS[nt][2] = -1e30f;
                if (col + 1 > row0 + 8) accS[nt][3] = -1e30f;
            }
        }

        // ---- online softmax + write P (hi/lo)
        {
            float mx0 = -1e30f, mx1 = -1e30f;
            #pragma unroll
            for (int nt = 0; nt < 8; nt++) {
                mx0 = fmaxf(mx0, fmaxf(accS[nt][0], accS[nt][1]));
                mx1 = fmaxf(mx1, fmaxf(accS[nt][2], accS[nt][3]));
            }
            mx0 = fmaxf(mx0, __shfl_xor_sync(0xffffffffu, mx0, 1));
            mx0 = fmaxf(mx0, __shfl_xor_sync(0xffffffffu, mx0, 2));
            mx1 = fmaxf(mx1, __shfl_xor_sync(0xffffffffu, mx1, 1));
            mx1 = fmaxf(mx1, __shfl_xor_sync(0xffffffffu, mx1, 2));

            float mn0 = fmaxf(m0, mx0), mn1 = fmaxf(m1, mx1);
            float al0 = __expf(m0 - mn0), al1 = __expf(m1 - mn1);
            m0 = mn0; m1 = mn1;

            char* prow0 = Psc + (wid * 16 + r0) * ASTR + c0 * 2;
            char* prow1 = prow0 + 8 * ASTR;
            float sum0 = 0.f, sum1 = 0.f;
            #pragma unroll
            for (int nt = 0; nt < 8; nt++) {
                float p0 = __expf(accS[nt][0] - mn0);
                float p1 = __expf(accS[nt][1] - mn0);
                float p2 = __expf(accS[nt][2] - mn1);
                float p3 = __expf(accS[nt][3] - mn1);
                sum0 += p0 + p1; sum1 += p2 + p3;
                __nv_bfloat16 h0 = __float2bfloat16(p0), h1 = __float2bfloat16(p1);
                __nv_bfloat16 h2 = __float2bfloat16(p2), h3 = __float2bfloat16(p3);
                __nv_bfloat16 g0 = __float2bfloat16(p0 - __bfloat162float(h0));
                __nv_bfloat16 g1 = __float2bfloat16(p1 - __bfloat162float(h1));
                __nv_bfloat16 g2 = __float2bfloat16(p2 - __bfloat162float(h2));
                __nv_bfloat16 g3 = __float2bfloat16(p3 - __bfloat162float(h3));
                *(uint32_t*)(prow0 + nt * 16)        = pack_bf2(h0, h1);
                *(uint32_t*)(prow0 + 128 + nt * 16)  = pack_bf2(g0, g1);
                *(uint32_t*)(prow1 + nt * 16)        = pack_bf2(h2, h3);
                *(uint32_t*)(prow1 + 128 + nt * 16)  = pack_bf2(g2, g3);
            }
            sum0 += __shfl_xor_sync(0xffffffffu, sum0, 1);
            sum0 += __shfl_xor_sync(0xffffffffu, sum0, 2);
            sum1 += __shfl_xor_sync(0xffffffffu, sum1, 1);
            sum1 += __shfl_xor_sync(0xffffffffu, sum1, 2);
            l0 = l0 * al0 + sum0;
            l1 = l1 * al1 + sum1;

            #pragma unroll
            for (int nt = 0; nt < 8; nt++) {
                accO[nt][0] *= al0; accO[nt][1] *= al0;
                accO[nt][2] *= al1; accO[nt][3] *= al1;
            }
        }
        __syncwarp();   // P written (intra-warp producer/consumer)

        // ---- O += P @ V (3-pass; V via ldmatrix.trans)
        #pragma unroll
        for (int pass = 0; pass < 3; pass++) {
            uint32_t aadd = (pass == 2) ? 128u : 0u;   // P lo
            uint32_t badd = (pass == 1) ? 128u : 0u;   // V lo
            #pragma unroll
            for (int ks = 0; ks < 4; ks++) {
                uint32_t pfr[4], vfr[4][4];
                ldm4(pfr, ps_b + aoff + aadd + ks * 32);
                #pragma unroll
                for (int n2 = 0; n2 < 4; n2++)
                    ldm4t(vfr[n2], vbuf + (uint32_t)(ks * 16 * ASTR) + voff + n2 * 32 + badd);
                #pragma unroll
                for (int nt = 0; nt < 8; nt++)
                    mma16816(accO[nt], pfr, &vfr[nt >> 1][(nt & 1) * 2]);
            }
        }
        __syncwarp();   // PV reads done before next P overwrite
    }

    // ---- normalize + store
    float inv0 = 1.f / l0, inv1 = 1.f / l1;
    int grow = qt * 64 + wid * 16 + r0;
    float* y0 = y + ((size_t)b * T_ + grow) * C_ + h * D_;
    float* y1 = y0 + 8 * C_;
    #pragma unroll
    for (int nt = 0; nt < 8; nt++) {
        int d = nt * 8 + c0;
        *(float2*)(y0 + d) = make_float2(accO[nt][0] * inv0, accO[nt][1] * inv0);
        *(float2*)(y1 + d) = make_float2(accO[nt][2] * inv1, accO[nt][3] * inv1);
    }
}

// ---------------------------------------------------------------------------
extern "C" void kernel_launch(void* const* d_in, const int* in_sizes, int n_in,
                              void* d_out, int out_size)
{
    const float* x     = (const float*)d_in[0];
    const float* Wqkv  = (const float*)d_in[1];
    const float* bqkv  = (const float*)d_in[2];
    const float* Wproj = (const float*)d_in[3];
    const float* bproj = (const float*)d_in[4];
    float* out = (float*)d_out;

    float *qkv_p = nullptr, *y_p = nullptr;
    __nv_bfloat16 *gA_p = nullptr, *gBq_p = nullptr, *gBp_p = nullptr;
    __nv_bfloat16 *q_p = nullptr, *k_p = nullptr, *v_p = nullptr;
    cudaGetSymbolAddress((void**)&qkv_p, g_qkv);
    cudaGetSymbolAddress((void**)&y_p,   g_y);
    cudaGetSymbolAddress((void**)&gA_p,  gA);
    cudaGetSymbolAddress((void**)&gBq_p, gBq);
    cudaGetSymbolAddress((void**)&gBp_p, gBp);
    cudaGetSymbolAddress((void**)&q_p,   gQsp);
    cudaGetSymbolAddress((void**)&k_p,   gKsp);
    cudaGetSymbolAddress((void**)&v_p,   gVsp);

    cudaFuncSetAttribute(attn_mma,
                         cudaFuncAttributeMaxDynamicSharedMemorySize, ATTN_SMEM);
    cudaFuncSetAttribute(gemm_tc,
                         cudaFuncAttributeMaxDynamicSharedMemorySize, GSMEM);

    // conversions
    convert_w<<<dim3(QKVN / 32, C_ / 32), 128>>>(Wqkv, gBq_p, QKVN);
    convert_w<<<dim3(C_ / 32, C_ / 32), 128>>>(Wproj, gBp_p, C_);
    convert_act<<<(M_ * C_ / 8) / 256, 256>>>(x, gA_p);

    // 1) QKV projection
    gemm_tc<<<dim3(QKVN / 128, M_ / 128), 256, GSMEM>>>(
        gA_p, gBq_p, bqkv, qkv_p, QKVN);

    // 1b) split qkv into per-(b,h) hi/lo bf16 arrays
    convert_qkv<<<(M_ * 384) / 256, 256>>>(qkv_p, q_p, k_p, v_p);

    // 2) causal flash attention (tensor cores)
    attn_mma<<<dim3(T_ / 64, B_ * H_), 128, ATTN_SMEM>>>(q_p, k_p, v_p, y_p);

    // 3) output projection
    convert_act<<<(M_ * C_ / 8) / 256, 256>>>(y_p, gA_p);
    gemm_tc<<<dim3(C_ / 128, M_ / 128), 256, GSMEM>>>(
        gA_p, gBp_p, bproj, out, C_);
}

// round 7
// speedup vs baseline: 2.3845x; 1.0302x over previous
#include <cuda_runtime.h>
#include <cuda_bf16.h>
#include <cstdint>
#include <math.h>

#define B_    2
#define T_    2048
#define C_    1024
#define H_    16
#define D_    64
#define M_    4096
#define QKVN  3072
#define KB_   3072            // expanded bf16 K (3 * 1024)
#define NIT   (KB_ / 32)      // 96 k-iterations of BK=32

// ---- scratch (__device__ globals; no allocation allowed) -------------------
__device__ __nv_bfloat16 gA[M_ * KB_];             // 24 MB expanded activations
__device__ __nv_bfloat16 gBq[QKVN * (size_t)KB_];  // 18 MB W_qkv^T expanded
__device__ __nv_bfloat16 gBp[C_ * (size_t)KB_];    // 6 MB  W_proj^T expanded
// per-(b,h) hi/lo split q,k,v: [bh][T][128] ([hi(64)|lo(64)] per token row)
__device__ __nv_bfloat16 gQsp[B_ * H_ * T_ * 128];
__device__ __nv_bfloat16 gKsp[B_ * H_ * T_ * 128];
__device__ __nv_bfloat16 gVsp[B_ * H_ * T_ * 128];

// ============================================================================
// small PTX helpers (all <= compute_80 features)
// ============================================================================
__device__ __forceinline__ uint32_t smem_u32(const void* p) {
    uint32_t a;
    asm("{ .reg .u64 t; cvta.to.shared.u64 t, %1; cvt.u32.u64 %0, t; }" : "=r"(a) : "l"(p));
    return a;
}
__device__ __forceinline__ void cp16(uint32_t dst, const void* src) {
    asm volatile("cp.async.cg.shared.global [%0], [%1], 16;" :: "r"(dst), "l"(src));
}
#define CP_COMMIT() asm volatile("cp.async.commit_group;" ::: "memory")
#define CP_WAIT2()  asm volatile("cp.async.wait_group 2;" ::: "memory")
#define CP_WAIT0()  asm volatile("cp.async.wait_group 0;" ::: "memory")

__device__ __forceinline__ void ldm4(uint32_t* r, uint32_t addr) {
    asm volatile("ldmatrix.sync.aligned.m8n8.x4.shared.b16 {%0,%1,%2,%3}, [%4];"
        : "=r"(r[0]), "=r"(r[1]), "=r"(r[2]), "=r"(r[3]) : "r"(addr));
}
__device__ __forceinline__ void ldm4t(uint32_t* r, uint32_t addr) {
    asm volatile("ldmatrix.sync.aligned.m8n8.x4.trans.shared.b16 {%0,%1,%2,%3}, [%4];"
        : "=r"(r[0]), "=r"(r[1]), "=r"(r[2]), "=r"(r[3]) : "r"(addr));
}
__device__ __forceinline__ void mma16816(float* c, const uint32_t* a, const uint32_t* b) {
    asm volatile(
        "mma.sync.aligned.m16n8k16.row.col.f32.bf16.bf16.f32 "
        "{%0,%1,%2,%3}, {%4,%5,%6,%7}, {%8,%9}, {%0,%1,%2,%3};"
        : "+f"(c[0]), "+f"(c[1]), "+f"(c[2]), "+f"(c[3])
        : "r"(a[0]), "r"(a[1]), "r"(a[2]), "r"(a[3]), "r"(b[0]), "r"(b[1]));
}
__device__ __forceinline__ uint32_t pack_bf2(__nv_bfloat16 lo, __nv_bfloat16 hi) {
    return ((uint32_t)__bfloat16_as_ushort(hi) << 16) | (uint32_t)__bfloat16_as_ushort(lo);
}

// ============================================================================
// Conversion kernels
// ============================================================================
// fp32 -> interleaved bf16 triplets for GEMM A-side: [hi, hi, lo]
__global__ __launch_bounds__(256) void convert_act(const float* __restrict__ x,
                                                   __nv_bfloat16* __restrict__ A) {
    int idx = blockIdx.x * 256 + threadIdx.x;
    int m  = idx >> 7;
    int kg = idx & 127;
    const float* p = x + (size_t)m * C_ + kg * 8;
    float4 v0 = *(const float4*)p;
    float4 v1 = *(const float4*)(p + 4);
    float v[8] = {v0.x, v0.y, v0.z, v0.w, v1.x, v1.y, v1.z, v1.w};
    union { __nv_bfloat16 h[24]; uint4 u[3]; } o;
    #pragma unroll
    for (int j = 0; j < 8; j++) {
        __nv_bfloat16 hi = __float2bfloat16(v[j]);
        __nv_bfloat16 lo = __float2bfloat16(v[j] - __bfloat162float(hi));
        o.h[3*j + 0] = hi; o.h[3*j + 1] = hi; o.h[3*j + 2] = lo;
    }
    uint4* dst = (uint4*)(A + (size_t)m * KB_ + kg * 24);
    dst[0] = o.u[0]; dst[1] = o.u[1]; dst[2] = o.u[2];
}

// W[K][N] fp32 -> Wp[N][3K] bf16 (transposed + expanded): [hi, lo, hi]
__global__ __launch_bounds__(128) void convert_w(const float* __restrict__ W,
                                                 __nv_bfloat16* __restrict__ Wp, int N) {
    __shared__ float s[32][33];
    int n0 = blockIdx.x * 32, k0 = blockIdx.y * 32;
    int t = threadIdx.x;
    {
        int kr = t >> 3, nc = (t & 7) * 4;
        #pragma unroll
        for (int i = 0; i < 2; i++) {
            int k = kr + i * 16;
            float4 v = *(const float4*)(W + (size_t)(k0 + k) * N + n0 + nc);
            s[k][nc] = v.x; s[k][nc+1] = v.y; s[k][nc+2] = v.z; s[k][nc+3] = v.w;
        }
    }
    __syncthreads();
    int nl = t >> 2, kg = t & 3;
    union { __nv_bfloat16 h[24]; uint4 u[3]; } o;
    #pragma unroll
    for (int j = 0; j < 8; j++) {
        float v = s[kg * 8 + j][nl];
        __nv_bfloat16 hi = __float2bfloat16(v);
        __nv_bfloat16 lo = __float2bfloat16(v - __bfloat162float(hi));
        o.h[3*j + 0] = hi; o.h[3*j + 1] = lo; o.h[3*j + 2] = hi;
    }
    uint4* dst = (uint4*)(Wp + (size_t)(n0 + nl) * KB_ + (size_t)(k0 + kg * 8) * 3);
    dst[0] = o.u[0]; dst[1] = o.u[1]; dst[2] = o.u[2];
}

// ============================================================================
// HMMA GEMM, 4-stage cp.async pipeline, 2 CTAs/SM.
// MODE 0: Co = A@B^T + bias (fp32 out).
// MODE 1: epilogue writes hi/lo-split q/k/v directly (Q pre-scaled by 1/8).
// ============================================================================
#define TSTR   80
#define TILEB  (128 * TSTR)
#define STAGEB (2 * TILEB)
#define GSMEM  (4 * STAGEB)     // 81920

template <int MODE>
__global__ __launch_bounds__(256, 2) void gemm_tc(
    const __nv_bfloat16* __restrict__ A, const __nv_bfloat16* __restrict__ Bw,
    const float* __restrict__ bias, float* __restrict__ Co, int Ntot,
    __nv_bfloat16* __restrict__ Qs, __nv_bfloat16* __restrict__ Ks,
    __nv_bfloat16* __restrict__ Vs)
{
    extern __shared__ char smemraw[];
    const uint32_t sb = smem_u32(smemraw);

    const int tid  = threadIdx.x;
    const int lane = tid & 31;
    const int wid  = tid >> 5;
    const int wr   = wid >> 2;
    const int wc   = wid & 3;
    const int brow = blockIdx.y * 128;
    const int bcol = blockIdx.x * 128;

    const __nv_bfloat16* Ag = A  + (size_t)brow * KB_;
    const __nv_bfloat16* Bg = Bw + (size_t)bcol * KB_;

    const int r0l = tid >> 2, ch0 = tid & 3;

    float acc[4][4][4];
    #pragma unroll
    for (int mt = 0; mt < 4; mt++)
        #pragma unroll
        for (int nt = 0; nt < 4; nt++)
            #pragma unroll
            for (int q = 0; q < 4; q++) acc[mt][nt][q] = 0.f;

    const int arow = (lane & 7) + ((lane >> 3) & 1) * 8;
    const int achk = lane >> 4;
    const int brw  = (lane & 7) + ((lane >> 4) & 1) * 8;
    const int bchk = (lane >> 3) & 1;
    const uint32_t aoff = (uint32_t)((wr * 64 + arow) * TSTR + achk * 16);
    const uint32_t boff = (uint32_t)(TILEB + (wc * 32 + brw) * TSTR + bchk * 16);

    auto load_stage = [&](int s, int buf) {
        const uint32_t base = sb + (uint32_t)buf * STAGEB;
        #pragma unroll
        for (int i = 0; i < 2; i++) {
            int row = r0l + i * 64;
            cp16(base + (uint32_t)(row * TSTR + ch0 * 16),
                 Ag + (size_t)row * KB_ + s * 32 + ch0 * 8);
            cp16(base + (uint32_t)(TILEB + row * TSTR + ch0 * 16),
                 Bg + (size_t)row * KB_ + s * 32 + ch0 * 8);
        }
    };

    load_stage(0, 0); CP_COMMIT();
    load_stage(1, 1); CP_COMMIT();
    load_stage(2, 2); CP_COMMIT();

    int buf = 0;
    #pragma unroll 1
    for (int s = 0; s < NIT; s++) {
        CP_WAIT2();
        __syncthreads();

        if (s + 3 < NIT) load_stage(s + 3, (s + 3) & 3);
        CP_COMMIT();

        const uint32_t base = sb + (uint32_t)buf * STAGEB;
        #pragma unroll
        for (int ks = 0; ks < 2; ks++) {
            uint32_t afr[4][4], bfr[2][4];
            #pragma unroll
            for (int mt = 0; mt < 4; mt++)
                ldm4(afr[mt], base + aoff + (uint32_t)(mt * 16 * TSTR + ks * 32));
            #pragma unroll
            for (int bt = 0; bt < 2; bt++)
                ldm4(bfr[bt], base + boff + (uint32_t)(bt * 16 * TSTR + ks * 32));
            #pragma unroll
            for (int mt = 0; mt < 4; mt++)
                #pragma unroll
                for (int nt = 0; nt < 4; nt++)
                    mma16816(acc[mt][nt], afr[mt], &bfr[nt >> 1][(nt & 1) * 2]);
        }
        buf = (buf + 1) & 3;
    }

    const int crow = lane >> 2;
    const int ccol = (lane & 3) * 2;

    if (MODE == 0) {
        #pragma unroll
        for (int nt = 0; nt < 4; nt++) {
            int col = bcol + wc * 32 + nt * 8 + ccol;
            float2 bi = *(const float2*)(bias + col);
            #pragma unroll
            for (int mt = 0; mt < 4; mt++) {
                int row = brow + wr * 64 + mt * 16 + crow;
                float2 v0 = make_float2(acc[mt][nt][0] + bi.x, acc[mt][nt][1] + bi.y);
                float2 v1 = make_float2(acc[mt][nt][2] + bi.x, acc[mt][nt][3] + bi.y);
                *(float2*)(Co + (size_t)row * Ntot + col)       = v0;
                *(float2*)(Co + (size_t)(row + 8) * Ntot + col) = v1;
            }
        }
    } else {
        // split-qkv epilogue: p = which of q/k/v, h = head, d = dim within head
        const int p  = bcol >> 10;
        __nv_bfloat16* outb = (p == 0) ? Qs : ((p == 1) ? Ks : Vs);
        const float sc = (p == 0) ? 0.125f : 1.f;
        const int hh = ((bcol + wc * 32) >> 6) & 15;
        const int dbase = (wc * 32) & 63;
        #pragma unroll
        for (int nt = 0; nt < 4; nt++) {
            int gcol = bcol + wc * 32 + nt * 8 + ccol;
            float2 bi = *(const float2*)(bias + gcol);
            int d = dbase + nt * 8 + ccol;     // even
            #pragma unroll
            for (int mt = 0; mt < 4; mt++) {
                int grow = brow + wr * 64 + mt * 16 + crow;
                #pragma unroll
                for (int half = 0; half < 2; half++) {
                    int m = grow + half * 8;
                    int bb = m >> 11, t = m & 2047;
                    float f0 = (acc[mt][nt][half * 2 + 0] + bi.x) * sc;
                    float f1 = (acc[mt][nt][half * 2 + 1] + bi.y) * sc;
                    __nv_bfloat16 h0 = __float2bfloat16(f0);
                    __nv_bfloat16 l0 = __float2bfloat16(f0 - __bfloat162float(h0));
                    __nv_bfloat16 h1 = __float2bfloat16(f1);
                    __nv_bfloat16 l1 = __float2bfloat16(f1 - __bfloat162float(h1));
                    char* row = (char*)(outb + (((size_t)(bb * H_ + hh) * T_) + t) * 128);
                    *(uint32_t*)(row + 2 * d)       = pack_bf2(h0, h1);
                    *(uint32_t*)(row + 128 + 2 * d) = pack_bf2(l0, l1);
                }
            }
        }
    }
}

// ============================================================================
// HMMA flash attention: pre-split inputs, cp.async double-buffered K/V,
// V via ldmatrix.trans. Epilogue writes [hi,hi,lo] triplets straight into gA.
// ============================================================================
#define ASTR  272
#define ATILE (64 * ASTR)
#define ATTN_SMEM (6 * ATILE)   // 104448 B

__global__ __launch_bounds__(128, 2) void attn_mma(
    const __nv_bfloat16* __restrict__ Qsp, const __nv_bfloat16* __restrict__ Ksp,
    const __nv_bfloat16* __restrict__ Vsp, __nv_bfloat16* __restrict__ Aout)
{
    extern __shared__ char smbuf[];
    const uint32_t sb   = smem_u32(smbuf);
    const uint32_t qs_b = sb;
    const uint32_t ps_b = sb + 5 * ATILE;
    char* Psc = smbuf + 5 * ATILE;

    const int tid  = threadIdx.x;
    const int lane = tid & 31;
    const int wid  = tid >> 5;
    const int qt   = (int)gridDim.x - 1 - (int)blockIdx.x;   // long CTAs first
    const int bh   = blockIdx.y;
    const int b = bh >> 4, h = bh & 15;

    const __nv_bfloat16* Qg = Qsp + ((size_t)bh * T_ + qt * 64) * 128;
    const __nv_bfloat16* Kg = Ksp + (size_t)bh * T_ * 128;
    const __nv_bfloat16* Vg = Vsp + (size_t)bh * T_ * 128;

    auto stage64 = [&](uint32_t sm, const __nv_bfloat16* g) {
        const char* gc = (const char*)g;
        #pragma unroll
        for (int i = 0; i < 8; i++) {
            int c = tid + 128 * i;
            cp16(sm + (uint32_t)((c >> 4) * ASTR + (c & 15) * 16),
                 gc + (c >> 4) * 256 + (c & 15) * 16);
        }
    };

    const int arow = (lane & 7) + ((lane >> 3) & 1) * 8;
    const int achk = lane >> 4;
    const uint32_t aoff = (uint32_t)((wid * 16 + arow) * ASTR + achk * 16);
    const int brw  = (lane & 7) + ((lane >> 4) & 1) * 8;
    const int bchk = (lane >> 3) & 1;
    uint32_t boffs[4];
    #pragma unroll
    for (int n2 = 0; n2 < 4; n2++)
        boffs[n2] = (uint32_t)((n2 * 16 + brw) * ASTR + bchk * 16);
    const uint32_t voff = (uint32_t)(arow * ASTR + achk * 16);

    stage64(qs_b, Qg);
    stage64(sb + 1 * ATILE, Kg);
    stage64(sb + 2 * ATILE, Vg);
    CP_COMMIT();

    float m0 = -1e30f, m1 = -1e30f, l0 = 0.f, l1 = 0.f;
    float accO[8][4];
    #pragma unroll
    for (int nt = 0; nt < 8; nt++)
        #pragma unroll
        for (int q = 0; q < 4; q++) accO[nt][q] = 0.f;

    const int r0 = lane >> 2;
    const int c0 = (lane & 3) * 2;
    const int row0 = wid * 16 + r0;

    #pragma unroll 1
    for (int kt = 0; kt <= qt; kt++) {
        CP_WAIT0();
        __syncthreads();
        const uint32_t kbuf = sb + (uint32_t)(1 + 2 * (kt & 1)) * ATILE;
        const uint32_t vbuf = kbuf + ATILE;

        if (kt < qt) {
            uint32_t nb = sb + (uint32_t)(1 + 2 * ((kt + 1) & 1)) * ATILE;
            stage64(nb,         Kg + (size_t)(kt + 1) * 64 * 128);
            stage64(nb + ATILE, Vg + (size_t)(kt + 1) * 64 * 128);
        }
        CP_COMMIT();

        float accS[8][4];
        #pragma unroll
        for (int nt = 0; nt < 8; nt++)
            #pragma unroll
            for (int q = 0; q < 4; q++) accS[nt][q] = 0.f;
        #pragma unroll
        for (int pass = 0; pass < 3; pass++) {
            uint32_t aadd = (pass == 2) ? 128u : 0u;
            uint32_t badd = (pass == 1) ? 128u : 0u;
            #pragma unroll
            for (int ks = 0; ks < 4; ks++) {
                uint32_t afr[4], bfr[4][4];
                ldm4(afr, qs_b + aoff + aadd + ks * 32);
                #pragma unroll
                for (int n2 = 0; n2 < 4; n2++)
                    ldm4(bfr[n2], kbuf + boffs[n2] + badd + ks * 32);
                #pragma unroll
                for (int nt = 0; nt < 8; nt++)
                    mma16816(accS[nt], afr, &bfr[nt >> 1][(nt & 1) * 2]);
            }
        }

        if (kt == qt) {
            #pragma unroll
            for (int nt = 0; nt < 8; nt++) {
                int col = nt * 8 + c0;
                if (col     > row0)     accS[nt][0] = -1e30f;
                if (col + 1 > row0)     accS[nt][1] = -1e30f;
                if (col     > row0 + 8) accS[nt][2] = -1e30f;
                if (col + 1 > row0 + 8) accS[nt][3] = -1e30f;
            }
        }

        {
            float mx0 = -1e30f, mx1 = -1e30f;
            #pragma unroll
            for (int nt = 0; nt < 8; nt++) {
                mx0 = fmaxf(mx0, fmaxf(accS[nt][0], accS[nt][1]));
                mx1 = fmaxf(mx1, fmaxf(accS[nt][2], accS[nt][3]));
            }
            mx0 = fmaxf(mx0, __shfl_xor_sync(0xffffffffu, mx0, 1));
            mx0 = fmaxf(mx0, __shfl_xor_sync(0xffffffffu, mx0, 2));
            mx1 = fmaxf(mx1, __shfl_xor_sync(0xffffffffu, mx1, 1));
            mx1 = fmaxf(mx1, __shfl_xor_sync(0xffffffffu, mx1, 2));

            float mn0 = fmaxf(m0, mx0), mn1 = fmaxf(m1, mx1);
            float al0 = __expf(m0 - mn0), al1 = __expf(m1 - mn1);
            m0 = mn0; m1 = mn1;

            char* prow0 = Psc + (wid * 16 + r0) * ASTR + c0 * 2;
            char* prow1 = prow0 + 8 * ASTR;
            float sum0 = 0.f, sum1 = 0.f;
            #pragma unroll
            for (int nt = 0; nt < 8; nt++) {
                float p0 = __expf(accS[nt][0] - mn0);
                float p1 = __expf(accS[nt][1] - mn0);
                float p2 = __expf(accS[nt][2] - mn1);
                float p3 = __expf(accS[nt][3] - mn1);
                sum0 += p0 + p1; sum1 += p2 + p3;
                __nv_bfloat16 h0 = __float2bfloat16(p0), h1 = __float2bfloat16(p1);
                __nv_bfloat16 h2 = __float2bfloat16(p2), h3 = __float2bfloat16(p3);
                __nv_bfloat16 g0 = __float2bfloat16(p0 - __bfloat162float(h0));
                __nv_bfloat16 g1 = __float2bfloat16(p1 - __bfloat162float(h1));
                __nv_bfloat16 g2 = __float2bfloat16(p2 - __bfloat162float(h2));
                __nv_bfloat16 g3 = __float2bfloat16(p3 - __bfloat162float(h3));
                *(uint32_t*)(prow0 + nt * 16)        = pack_bf2(h0, h1);
                *(uint32_t*)(prow0 + 128 + nt * 16)  = pack_bf2(g0, g1);
                *(uint32_t*)(prow1 + nt * 16)        = pack_bf2(h2, h3);
                *(uint32_t*)(prow1 + 128 + nt * 16)  = pack_bf2(g2, g3);
            }
            sum0 += __shfl_xor_sync(0xffffffffu, sum0, 1);
            sum0 += __shfl_xor_sync(0xffffffffu, sum0, 2);
            sum1 += __shfl_xor_sync(0xffffffffu, sum1, 1);
            sum1 += __shfl_xor_sync(0xffffffffu, sum1, 2);
            l0 = l0 * al0 + sum0;
            l1 = l1 * al1 + sum1;

            #pragma unroll
            for (int nt = 0; nt < 8; nt++) {
                accO[nt][0] *= al0; accO[nt][1] *= al0;
                accO[nt][2] *= al1; accO[nt][3] *= al1;
            }
        }
        __syncwarp();

        #pragma unroll
        for (int pass = 0; pass < 3; pass++) {
            uint32_t aadd = (pass == 2) ? 128u : 0u;
            uint32_t badd = (pass == 1) ? 128u : 0u;
            #pragma unroll
            for (int ks = 0; ks < 4; ks++) {
                uint32_t pfr[4], vfr[4][4];
                ldm4(pfr, ps_b + aoff + aadd + ks * 32);
                #pragma unroll
                for (int n2 = 0; n2 < 4; n2++)
                    ldm4t(vfr[n2], vbuf + (uint32_t)(ks * 16 * ASTR) + voff + n2 * 32 + badd);
                #pragma unroll
                for (int nt = 0; nt < 8; nt++)
                    mma16816(accO[nt], pfr, &vfr[nt >> 1][(nt & 1) * 2]);
            }
        }
        __syncwarp();
    }

    // ---- normalize + write [hi,hi,lo] triplets straight into gA (proj input)
    float inv0 = 1.f / l0, inv1 = 1.f / l1;
    int grow = qt * 64 + wid * 16 + r0;
    size_t mrow = (size_t)b * T_ + grow;
    char* rp0 = (char*)(Aout + mrow * KB_);
    char* rp1 = (char*)(Aout + (mrow + 8) * KB_);
    #pragma unroll
    for (int nt = 0; nt < 8; nt++) {
        int d = nt * 8 + c0;            // even
        int k0 = h * D_ + d;            // even -> byte offset 6*k0 is 4-aligned
        float f0 = accO[nt][0] * inv0, f1 = accO[nt][1] * inv0;
        float f2 = accO[nt][2] * inv1, f3 = accO[nt][3] * inv1;
        __nv_bfloat16 h0 = __float2bfloat16(f0);
        __nv_bfloat16 e0 = __float2bfloat16(f0 - __bfloat162float(h0));
        __nv_bfloat16 h1 = __float2bfloat16(f1);
        __nv_bfloat16 e1 = __float2bfloat16(f1 - __bfloat162float(h1));
        __nv_bfloat16 h2 = __float2bfloat16(f2);
        __nv_bfloat16 e2 = __float2bfloat16(f2 - __bfloat162float(h2));
        __nv_bfloat16 h3 = __float2bfloat16(f3);
        __nv_bfloat16 e3 = __float2bfloat16(f3 - __bfloat162float(h3));
        char* d0 = rp0 + 6 * k0;
        *(uint32_t*)(d0 + 0) = pack_bf2(h0, h0);
        *(uint32_t*)(d0 + 4) = pack_bf2(e0, h1);
        *(uint32_t*)(d0 + 8) = pack_bf2(h1, e1);
        char* d1 = rp1 + 6 * k0;
        *(uint32_t*)(d1 + 0) = pack_bf2(h2, h2);
        *(uint32_t*)(d1 + 4) = pack_bf2(e2, h3);
        *(uint32_t*)(d1 + 8) = pack_bf2(h3, e3);
    }
}

// ---------------------------------------------------------------------------
extern "C" void kernel_launch(void* const* d_in, const int* in_sizes, int n_in,
                              void* d_out, int out_size)
{
    const float* x     = (const float*)d_in[0];
    const float* Wqkv  = (const float*)d_in[1];
    const float* bqkv  = (const float*)d_in[2];
    const float* Wproj = (const float*)d_in[3];
    const float* bproj = (const float*)d_in[4];
    float* out = (float*)d_out;

    __nv_bfloat16 *gA_p = nullptr, *gBq_p = nullptr, *gBp_p = nullptr;
    __nv_bfloat16 *q_p = nullptr, *k_p = nullptr, *v_p = nullptr;
    cudaGetSymbolAddress((void**)&gA_p,  gA);
    cudaGetSymbolAddress((void**)&gBq_p, gBq);
    cudaGetSymbolAddress((void**)&gBp_p, gBp);
    cudaGetSymbolAddress((void**)&q_p,   gQsp);
    cudaGetSymbolAddress((void**)&k_p,   gKsp);
    cudaGetSymbolAddress((void**)&v_p,   gVsp);

    cudaFuncSetAttribute(attn_mma,
                         cudaFuncAttributeMaxDynamicSharedMemorySize, ATTN_SMEM);
    cudaFuncSetAttribute(gemm_tc<0>,
                         cudaFuncAttributeMaxDynamicSharedMemorySize, GSMEM);
    cudaFuncSetAttribute(gemm_tc<1>,
                         cudaFuncAttributeMaxDynamicSharedMemorySize, GSMEM);

    // conversions
    convert_w<<<dim3(QKVN / 32, C_ / 32), 128>>>(Wqkv, gBq_p, QKVN);
    convert_w<<<dim3(C_ / 32, C_ / 32), 128>>>(Wproj, gBp_p, C_);
    convert_act<<<(M_ * C_ / 8) / 256, 256>>>(x, gA_p);

    // 1) QKV projection, fused split-qkv epilogue
    gemm_tc<1><<<dim3(QKVN / 128, M_ / 128), 256, GSMEM>>>(
        gA_p, gBq_p, bqkv, nullptr, QKVN, q_p, k_p, v_p);

    // 2) causal flash attention; epilogue writes proj-input triplets into gA
    attn_mma<<<dim3(T_ / 64, B_ * H_), 128, ATTN_SMEM>>>(q_p, k_p, v_p, gA_p);

    // 3) output projection
    gemm_tc<0><<<dim3(C_ / 128, M_ / 128), 256, GSMEM>>>(
        gA_p, gBp_p, bproj, out, C_, nullptr, nullptr, nullptr);
}

// round 8
// speedup vs baseline: 2.6793x; 1.1237x over previous
#include <cuda_runtime.h>
#include <cuda_bf16.h>
#include <cstdint>
#include <math.h>

#define B_    2
#define T_    2048
#define C_    1024
#define H_    16
#define D_    64
#define M_    4096
#define QKVN  3072
#define KB_   3072            // expanded bf16 K (3 * 1024)
#define NIT   (KB_ / 32)      // 96 k-iterations of BK=32

// ---- scratch (__device__ globals; no allocation allowed) -------------------
__device__ __nv_bfloat16 gA[M_ * KB_];             // 24 MB expanded activations
__device__ __nv_bfloat16 gBq[QKVN * (size_t)KB_];  // 18 MB W_qkv^T expanded
__device__ __nv_bfloat16 gBp[C_ * (size_t)KB_];    // 6 MB  W_proj^T expanded
// per-(b,h) hi/lo split q,k,v: [bh][T][128] ([hi(64)|lo(64)] per token row)
__device__ __nv_bfloat16 gQsp[B_ * H_ * T_ * 128];
__device__ __nv_bfloat16 gKsp[B_ * H_ * T_ * 128];
__device__ __nv_bfloat16 gVsp[B_ * H_ * T_ * 128];

// ============================================================================
// small PTX helpers (all <= compute_80 features)
// ============================================================================
__device__ __forceinline__ uint32_t smem_u32(const void* p) {
    uint32_t a;
    asm("{ .reg .u64 t; cvta.to.shared.u64 t, %1; cvt.u32.u64 %0, t; }" : "=r"(a) : "l"(p));
    return a;
}
__device__ __forceinline__ void cp16(uint32_t dst, const void* src) {
    asm volatile("cp.async.cg.shared.global [%0], [%1], 16;" :: "r"(dst), "l"(src));
}
#define CP_COMMIT() asm volatile("cp.async.commit_group;" ::: "memory")
#define CP_WAIT2()  asm volatile("cp.async.wait_group 2;" ::: "memory")
#define CP_WAIT0()  asm volatile("cp.async.wait_group 0;" ::: "memory")

__device__ __forceinline__ void ldm4(uint32_t* r, uint32_t addr) {
    asm volatile("ldmatrix.sync.aligned.m8n8.x4.shared.b16 {%0,%1,%2,%3}, [%4];"
        : "=r"(r[0]), "=r"(r[1]), "=r"(r[2]), "=r"(r[3]) : "r"(addr));
}
__device__ __forceinline__ void ldm4t(uint32_t* r, uint32_t addr) {
    asm volatile("ldmatrix.sync.aligned.m8n8.x4.trans.shared.b16 {%0,%1,%2,%3}, [%4];"
        : "=r"(r[0]), "=r"(r[1]), "=r"(r[2]), "=r"(r[3]) : "r"(addr));
}
__device__ __forceinline__ void mma16816(float* c, const uint32_t* a, const uint32_t* b) {
    asm volatile(
        "mma.sync.aligned.m16n8k16.row.col.f32.bf16.bf16.f32 "
        "{%0,%1,%2,%3}, {%4,%5,%6,%7}, {%8,%9}, {%0,%1,%2,%3};"
        : "+f"(c[0]), "+f"(c[1]), "+f"(c[2]), "+f"(c[3])
        : "r"(a[0]), "r"(a[1]), "r"(a[2]), "r"(a[3]), "r"(b[0]), "r"(b[1]));
}
__device__ __forceinline__ uint32_t pack_bf2(__nv_bfloat16 lo, __nv_bfloat16 hi) {
    return ((uint32_t)__bfloat16_as_ushort(hi) << 16) | (uint32_t)__bfloat16_as_ushort(lo);
}

// ============================================================================
// Conversion kernels
// ============================================================================
// fp32 -> interleaved bf16 triplets for GEMM A-side: [hi, hi, lo]
__global__ __launch_bounds__(256) void convert_act(const float* __restrict__ x,
                                                   __nv_bfloat16* __restrict__ A) {
    int idx = blockIdx.x * 256 + threadIdx.x;
    int m  = idx >> 7;
    int kg = idx & 127;
    const float* p = x + (size_t)m * C_ + kg * 8;
    float4 v0 = *(const float4*)p;
    float4 v1 = *(const float4*)(p + 4);
    float v[8] = {v0.x, v0.y, v0.z, v0.w, v1.x, v1.y, v1.z, v1.w};
    union { __nv_bfloat16 h[24]; uint4 u[3]; } o;
    #pragma unroll
    for (int j = 0; j < 8; j++) {
        __nv_bfloat16 hi = __float2bfloat16(v[j]);
        __nv_bfloat16 lo = __float2bfloat16(v[j] - __bfloat162float(hi));
        o.h[3*j + 0] = hi; o.h[3*j + 1] = hi; o.h[3*j + 2] = lo;
    }
    uint4* dst = (uint4*)(A + (size_t)m * KB_ + kg * 24);
    dst[0] = o.u[0]; dst[1] = o.u[1]; dst[2] = o.u[2];
}

// W[K][N] fp32 -> Wp[N][3K] bf16 (transposed + expanded): [hi, lo, hi]
__global__ __launch_bounds__(128) void convert_w(const float* __restrict__ W,
                                                 __nv_bfloat16* __restrict__ Wp, int N) {
    __shared__ float s[32][33];
    int n0 = blockIdx.x * 32, k0 = blockIdx.y * 32;
    int t = threadIdx.x;
    {
        int kr = t >> 3, nc = (t & 7) * 4;
        #pragma unroll
        for (int i = 0; i < 2; i++) {
            int k = kr + i * 16;
            float4 v = *(const float4*)(W + (size_t)(k0 + k) * N + n0 + nc);
            s[k][nc] = v.x; s[k][nc+1] = v.y; s[k][nc+2] = v.z; s[k][nc+3] = v.w;
        }
    }
    __syncthreads();
    int nl = t >> 2, kg = t & 3;
    union { __nv_bfloat16 h[24]; uint4 u[3]; } o;
    #pragma unroll
    for (int j = 0; j < 8; j++) {
        float v = s[kg * 8 + j][nl];
        __nv_bfloat16 hi = __float2bfloat16(v);
        __nv_bfloat16 lo = __float2bfloat16(v - __bfloat162float(hi));
        o.h[3*j + 0] = hi; o.h[3*j + 1] = lo; o.h[3*j + 2] = hi;
    }
    uint4* dst = (uint4*)(Wp + (size_t)(n0 + nl) * KB_ + (size_t)(k0 + kg * 8) * 3);
    dst[0] = o.u[0]; dst[1] = o.u[1]; dst[2] = o.u[2];
}

// ============================================================================
// HMMA GEMM: CTA 128x128, 4 warps (2x2), warp tile 64x64, BK=32, 4-stage
// cp.async pipeline, 2 CTAs/SM. Higher fragment reuse (mma:ldsm = 4:1).
// MODE 0: Co = A@B^T + bias (fp32). MODE 1: hi/lo-split q/k/v epilogue.
// ============================================================================
#define TSTR   80
#define TILEB  (128 * TSTR)
#define STAGEB (2 * TILEB)
#define GSMEM  (4 * STAGEB)     // 81920

template <int MODE>
__global__ __launch_bounds__(128, 2) void gemm_tc(
    const __nv_bfloat16* __restrict__ A, const __nv_bfloat16* __restrict__ Bw,
    const float* __restrict__ bias, float* __restrict__ Co, int Ntot,
    __nv_bfloat16* __restrict__ Qs, __nv_bfloat16* __restrict__ Ks,
    __nv_bfloat16* __restrict__ Vs)
{
    extern __shared__ char smemraw[];
    const uint32_t sb = smem_u32(smemraw);

    const int tid  = threadIdx.x;
    const int lane = tid & 31;
    const int wid  = tid >> 5;
    const int wr   = wid >> 1;          // 0..1 -> 64 rows
    const int wc   = wid & 1;           // 0..1 -> 64 cols
    const int brow = blockIdx.y * 128;
    const int bcol = blockIdx.x * 128;

    const __nv_bfloat16* Ag = A  + (size_t)brow * KB_;
    const __nv_bfloat16* Bg = Bw + (size_t)bcol * KB_;

    const int r0l = tid >> 2, ch0 = tid & 3;

    float acc[4][8][4];
    #pragma unroll
    for (int mt = 0; mt < 4; mt++)
        #pragma unroll
        for (int nt = 0; nt < 8; nt++)
            #pragma unroll
            for (int q = 0; q < 4; q++) acc[mt][nt][q] = 0.f;

    const int arow = (lane & 7) + ((lane >> 3) & 1) * 8;
    const int achk = lane >> 4;
    const int brw  = (lane & 7) + ((lane >> 4) & 1) * 8;
    const int bchk = (lane >> 3) & 1;
    const uint32_t aoff = (uint32_t)((wr * 64 + arow) * TSTR + achk * 16);
    const uint32_t boff = (uint32_t)(TILEB + (wc * 64 + brw) * TSTR + bchk * 16);

    auto load_stage = [&](int s, int buf) {
        const uint32_t base = sb + (uint32_t)buf * STAGEB;
        #pragma unroll
        for (int i = 0; i < 4; i++) {
            int row = r0l + i * 32;
            cp16(base + (uint32_t)(row * TSTR + ch0 * 16),
                 Ag + (size_t)row * KB_ + s * 32 + ch0 * 8);
            cp16(base + (uint32_t)(TILEB + row * TSTR + ch0 * 16),
                 Bg + (size_t)row * KB_ + s * 32 + ch0 * 8);
        }
    };

    load_stage(0, 0); CP_COMMIT();
    load_stage(1, 1); CP_COMMIT();
    load_stage(2, 2); CP_COMMIT();

    int buf = 0;
    #pragma unroll 1
    for (int s = 0; s < NIT; s++) {
        CP_WAIT2();
        __syncthreads();

        if (s + 3 < NIT) load_stage(s + 3, (s + 3) & 3);
        CP_COMMIT();

        const uint32_t base = sb + (uint32_t)buf * STAGEB;
        #pragma unroll
        for (int ks = 0; ks < 2; ks++) {
            uint32_t afr[4][4], bfr[4][4];
            #pragma unroll
            for (int mt = 0; mt < 4; mt++)
                ldm4(afr[mt], base + aoff + (uint32_t)(mt * 16 * TSTR + ks * 32));
            #pragma unroll
            for (int n2 = 0; n2 < 4; n2++)
                ldm4(bfr[n2], base + boff + (uint32_t)(n2 * 16 * TSTR + ks * 32));
            #pragma unroll
            for (int mt = 0; mt < 4; mt++)
                #pragma unroll
                for (int nt = 0; nt < 8; nt++)
                    mma16816(acc[mt][nt], afr[mt], &bfr[nt >> 1][(nt & 1) * 2]);
        }
        buf = (buf + 1) & 3;
    }

    const int crow = lane >> 2;
    const int ccol = (lane & 3) * 2;

    if (MODE == 0) {
        #pragma unroll
        for (int nt = 0; nt < 8; nt++) {
            int col = bcol + wc * 64 + nt * 8 + ccol;
            float2 bi = *(const float2*)(bias + col);
            #pragma unroll
            for (int mt = 0; mt < 4; mt++) {
                int row = brow + wr * 64 + mt * 16 + crow;
                float2 v0 = make_float2(acc[mt][nt][0] + bi.x, acc[mt][nt][1] + bi.y);
                float2 v1 = make_float2(acc[mt][nt][2] + bi.x, acc[mt][nt][3] + bi.y);
                *(float2*)(Co + (size_t)row * Ntot + col)       = v0;
                *(float2*)(Co + (size_t)(row + 8) * Ntot + col) = v1;
            }
        }
    } else {
        // split-qkv epilogue: warp's 64 cols = exactly one head
        const int p  = bcol >> 10;
        __nv_bfloat16* outb = (p == 0) ? Qs : ((p == 1) ? Ks : Vs);
        const float sc = (p == 0) ? 0.125f : 1.f;
        const int hh = ((bcol + wc * 64) >> 6) & 15;
        #pragma unroll
        for (int nt = 0; nt < 8; nt++) {
            int gcol = bcol + wc * 64 + nt * 8 + ccol;
            float2 bi = *(const float2*)(bias + gcol);
            int d = nt * 8 + ccol;     // even, within head
            #pragma unroll
            for (int mt = 0; mt < 4; mt++) {
                int grow = brow + wr * 64 + mt * 16 + crow;
                #pragma unroll
                for (int half = 0; half < 2; half++) {
                    int m = grow + half * 8;
                    int bb = m >> 11, t = m & 2047;
                    float f0 = (acc[mt][nt][half * 2 + 0] + bi.x) * sc;
                    float f1 = (acc[mt][nt][half * 2 + 1] + bi.y) * sc;
                    __nv_bfloat16 h0 = __float2bfloat16(f0);
                    __nv_bfloat16 l0 = __float2bfloat16(f0 - __bfloat162float(h0));
                    __nv_bfloat16 h1 = __float2bfloat16(f1);
                    __nv_bfloat16 l1 = __float2bfloat16(f1 - __bfloat162float(h1));
                    char* row = (char*)(outb + (((size_t)(bb * H_ + hh) * T_) + t) * 128);
                    *(uint32_t*)(row + 2 * d)       = pack_bf2(h0, h1);
                    *(uint32_t*)(row + 128 + 2 * d) = pack_bf2(l0, l1);
                }
            }
        }
    }
}

// ============================================================================
// HMMA flash attention (unchanged from R7)
// ============================================================================
#define ASTR  272
#define ATILE (64 * ASTR)
#define ATTN_SMEM (6 * ATILE)   // 104448 B

__global__ __launch_bounds__(128, 2) void attn_mma(
    const __nv_bfloat16* __restrict__ Qsp, const __nv_bfloat16* __restrict__ Ksp,
    const __nv_bfloat16* __restrict__ Vsp, __nv_bfloat16* __restrict__ Aout)
{
    extern __shared__ char smbuf[];
    const uint32_t sb   = smem_u32(smbuf);
    const uint32_t qs_b = sb;
    const uint32_t ps_b = sb + 5 * ATILE;
    char* Psc = smbuf + 5 * ATILE;

    const int tid  = threadIdx.x;
    const int lane = tid & 31;
    const int wid  = tid >> 5;
    const int qt   = (int)gridDim.x - 1 - (int)blockIdx.x;
    const int bh   = blockIdx.y;
    const int b = bh >> 4, h = bh & 15;

    const __nv_bfloat16* Qg = Qsp + ((size_t)bh * T_ + qt * 64) * 128;
    const __nv_bfloat16* Kg = Ksp + (size_t)bh * T_ * 128;
    const __nv_bfloat16* Vg = Vsp + (size_t)bh * T_ * 128;

    auto stage64 = [&](uint32_t sm, const __nv_bfloat16* g) {
        const char* gc = (const char*)g;
        #pragma unroll
        for (int i = 0; i < 8; i++) {
            int c = tid + 128 * i;
            cp16(sm + (uint32_t)((c >> 4) * ASTR + (c & 15) * 16),
                 gc + (c >> 4) * 256 + (c & 15) * 16);
        }
    };

    const int arow = (lane & 7) + ((lane >> 3) & 1) * 8;
    const int achk = lane >> 4;
    const uint32_t aoff = (uint32_t)((wid * 16 + arow) * ASTR + achk * 16);
    const int brw  = (lane & 7) + ((lane >> 4) & 1) * 8;
    const int bchk = (lane >> 3) & 1;
    uint32_t boffs[4];
    #pragma unroll
    for (int n2 = 0; n2 < 4; n2++)
        boffs[n2] = (uint32_t)((n2 * 16 + brw) * ASTR + bchk * 16);
    const uint32_t voff = (uint32_t)(arow * ASTR + achk * 16);

    stage64(qs_b, Qg);
    stage64(sb + 1 * ATILE, Kg);
    stage64(sb + 2 * ATILE, Vg);
    CP_COMMIT();

    float m0 = -1e30f, m1 = -1e30f, l0 = 0.f, l1 = 0.f;
    float accO[8][4];
    #pragma unroll
    for (int nt = 0; nt < 8; nt++)
        #pragma unroll
        for (int q = 0; q < 4; q++) accO[nt][q] = 0.f;

    const int r0 = lane >> 2;
    const int c0 = (lane & 3) * 2;
    const int row0 = wid * 16 + r0;

    #pragma unroll 1
    for (int kt = 0; kt <= qt; kt++) {
        CP_WAIT0();
        __syncthreads();
        const uint32_t kbuf = sb + (uint32_t)(1 + 2 * (kt & 1)) * ATILE;
        const uint32_t vbuf = kbuf + ATILE;

        if (kt < qt) {
            uint32_t nb = sb + (uint32_t)(1 + 2 * ((kt + 1) & 1)) * ATILE;
            stage64(nb,         Kg + (size_t)(kt + 1) * 64 * 128);
            stage64(nb + ATILE, Vg + (size_t)(kt + 1) * 64 * 128);
        }
        CP_COMMIT();

        float accS[8][4];
        #pragma unroll
        for (int nt = 0; nt < 8; nt++)
            #pragma unroll
            for (int q = 0; q < 4; q++) accS[nt][q] = 0.f;
        #pragma unroll
        for (int pass = 0; pass < 3; pass++) {
            uint32_t aadd = (pass == 2) ? 128u : 0u;
            uint32_t badd = (pass == 1) ? 128u : 0u;
            #pragma unroll
            for (int ks = 0; ks < 4; ks++) {
                uint32_t afr[4], bfr[4][4];
                ldm4(afr, qs_b + aoff + aadd + ks * 32);
                #pragma unroll
                for (int n2 = 0; n2 < 4; n2++)
                    ldm4(bfr[n2], kbuf + boffs[n2] + badd + ks * 32);
                #pragma unroll
                for (int nt = 0; nt < 8; nt++)
                    mma16816(accS[nt], afr, &bfr[nt >> 1][(nt & 1) * 2]);
            }
        }

        if (kt == qt) {
            #pragma unroll
            for (int nt = 0; nt < 8; nt++) {
                int col = nt * 8 + c0;
                if (col     > row0)     accS[nt][0] = -1e30f;
                if (col + 1 > row0)     accS[nt][1] = -1e30f;
                if (col     > row0 + 8) accS[nt][2] = -1e30f;
                if (col + 1 > row0 + 8) accS[nt][3] = -1e30f;
            }
        }

        {
            float mx0 = -1e30f, mx1 = -1e30f;
            #pragma unroll
            for (int nt = 0; nt < 8; nt++) {
                mx0 = fmaxf(mx0, fmaxf(accS[nt][0], accS[nt][1]));
                mx1 = fmaxf(mx1, fmaxf(accS[nt][2], accS[nt][3]));
            }
            mx0 = fmaxf(mx0, __shfl_xor_sync(0xffffffffu, mx0, 1));
            mx0 = fmaxf(mx0, __shfl_xor_sync(0xffffffffu, mx0, 2));
            mx1 = fmaxf(mx1, __shfl_xor_sync(0xffffffffu, mx1, 1));
            mx1 = fmaxf(mx1, __shfl_xor_sync(0xffffffffu, mx1, 2));

            float mn0 = fmaxf(m0, mx0), mn1 = fmaxf(m1, mx1);
            float al0 = __expf(m0 - mn0), al1 = __expf(m1 - mn1);
            m0 = mn0; m1 = mn1;

            char* prow0 = Psc + (wid * 16 + r0) * ASTR + c0 * 2;
            char* prow1 = prow0 + 8 * ASTR;
            float sum0 = 0.f, sum1 = 0.f;
            #pragma unroll
            for (int nt = 0; nt < 8; nt++) {
                float p0 = __expf(accS[nt][0] - mn0);
                float p1 = __expf(accS[nt][1] - mn0);
                float p2 = __expf(accS[nt][2] - mn1);
                float p3 = __expf(accS[nt][3] - mn1);
                sum0 += p0 + p1; sum1 += p2 + p3;
                __nv_bfloat16 h0 = __float2bfloat16(p0), h1 = __float2bfloat16(p1);
                __nv_bfloat16 h2 = __float2bfloat16(p2), h3 = __float2bfloat16(p3);
                __nv_bfloat16 g0 = __float2bfloat16(p0 - __bfloat162float(h0));
                __nv_bfloat16 g1 = __float2bfloat16(p1 - __bfloat162float(h1));
                __nv_bfloat16 g2 = __float2bfloat16(p2 - __bfloat162float(h2));
                __nv_bfloat16 g3 = __float2bfloat16(p3 - __bfloat162float(h3));
                *(uint32_t*)(prow0 + nt * 16)        = pack_bf2(h0, h1);
                *(uint32_t*)(prow0 + 128 + nt * 16)  = pack_bf2(g0, g1);
                *(uint32_t*)(prow1 + nt * 16)        = pack_bf2(h2, h3);
                *(uint32_t*)(prow1 + 128 + nt * 16)  = pack_bf2(g2, g3);
            }
            sum0 += __shfl_xor_sync(0xffffffffu, sum0, 1);
            sum0 += __shfl_xor_sync(0xffffffffu, sum0, 2);
            sum1 += __shfl_xor_sync(0xffffffffu, sum1, 1);
            sum1 += __shfl_xor_sync(0xffffffffu, sum1, 2);
            l0 = l0 * al0 + sum0;
            l1 = l1 * al1 + sum1;

            #pragma unroll
            for (int nt = 0; nt < 8; nt++) {
                accO[nt][0] *= al0; accO[nt][1] *= al0;
                accO[nt][2] *= al1; accO[nt][3] *= al1;
            }
        }
        __syncwarp();

        #pragma unroll
        for (int pass = 0; pass < 3; pass++) {
            uint32_t aadd = (pass == 2) ? 128u : 0u;
            uint32_t badd = (pass == 1) ? 128u : 0u;
            #pragma unroll
            for (int ks = 0; ks < 4; ks++) {
                uint32_t pfr[4], vfr[4][4];
                ldm4(pfr, ps_b + aoff + aadd + ks * 32);
                #pragma unroll
                for (int n2 = 0; n2 < 4; n2++)
                    ldm4t(vfr[n2], vbuf + (uint32_t)(ks * 16 * ASTR) + voff + n2 * 32 + badd);
                #pragma unroll
                for (int nt = 0; nt < 8; nt++)
                    mma16816(accO[nt], pfr, &vfr[nt >> 1][(nt & 1) * 2]);
            }
        }
        __syncwarp();
    }

    float inv0 = 1.f / l0, inv1 = 1.f / l1;
    int grow = qt * 64 + wid * 16 + r0;
    size_t mrow = (size_t)b * T_ + grow;
    char* rp0 = (char*)(Aout + mrow * KB_);
    char* rp1 = (char*)(Aout + (mrow + 8) * KB_);
    #pragma unroll
    for (int nt = 0; nt < 8; nt++) {
        int d = nt * 8 + c0;
        int k0 = h * D_ + d;
        float f0 = accO[nt][0] * inv0, f1 = accO[nt][1] * inv0;
        float f2 = accO[nt][2] * inv1, f3 = accO[nt][3] * inv1;
        __nv_bfloat16 h0 = __float2bfloat16(f0);
        __nv_bfloat16 e0 = __float2bfloat16(f0 - __bfloat162float(h0));
        __nv_bfloat16 h1 = __float2bfloat16(f1);
        __nv_bfloat16 e1 = __float2bfloat16(f1 - __bfloat162float(h1));
        __nv_bfloat16 h2 = __float2bfloat16(f2);
        __nv_bfloat16 e2 = __float2bfloat16(f2 - __bfloat162float(h2));
        __nv_bfloat16 h3 = __float2bfloat16(f3);
        __nv_bfloat16 e3 = __float2bfloat16(f3 - __bfloat162float(h3));
        char* d0 = rp0 + 6 * k0;
        *(uint32_t*)(d0 + 0) = pack_bf2(h0, h0);
        *(uint32_t*)(d0 + 4) = pack_bf2(e0, h1);
        *(uint32_t*)(d0 + 8) = pack_bf2(h1, e1);
        char* d1 = rp1 + 6 * k0;
        *(uint32_t*)(d1 + 0) = pack_bf2(h2, h2);
        *(uint32_t*)(d1 + 4) = pack_bf2(e2, h3);
        *(uint32_t*)(d1 + 8) = pack_bf2(h3, e3);
    }
}

// ---------------------------------------------------------------------------
extern "C" void kernel_launch(void* const* d_in, const int* in_sizes, int n_in,
                              void* d_out, int out_size)
{
    const float* x     = (const float*)d_in[0];
    const float* Wqkv  = (const float*)d_in[1];
    const float* bqkv  = (const float*)d_in[2];
    const float* Wproj = (const float*)d_in[3];
    const float* bproj = (const float*)d_in[4];
    float* out = (float*)d_out;

    __nv_bfloat16 *gA_p = nullptr, *gBq_p = nullptr, *gBp_p = nullptr;
    __nv_bfloat16 *q_p = nullptr, *k_p = nullptr, *v_p = nullptr;
    cudaGetSymbolAddress((void**)&gA_p,  gA);
    cudaGetSymbolAddress((void**)&gBq_p, gBq);
    cudaGetSymbolAddress((void**)&gBp_p, gBp);
    cudaGetSymbolAddress((void**)&q_p,   gQsp);
    cudaGetSymbolAddress((void**)&k_p,   gKsp);
    cudaGetSymbolAddress((void**)&v_p,   gVsp);

    cudaFuncSetAttribute(attn_mma,
                         cudaFuncAttributeMaxDynamicSharedMemorySize, ATTN_SMEM);
    cudaFuncSetAttribute(gemm_tc<0>,
                         cudaFuncAttributeMaxDynamicSharedMemorySize, GSMEM);
    cudaFuncSetAttribute(gemm_tc<1>,
                         cudaFuncAttributeMaxDynamicSharedMemorySize, GSMEM);

    // conversions
    convert_w<<<dim3(QKVN / 32, C_ / 32), 128>>>(Wqkv, gBq_p, QKVN);
    convert_w<<<dim3(C_ / 32, C_ / 32), 128>>>(Wproj, gBp_p, C_);
    convert_act<<<(M_ * C_ / 8) / 256, 256>>>(x, gA_p);

    // 1) QKV projection, fused split-qkv epilogue
    gemm_tc<1><<<dim3(QKVN / 128, M_ / 128), 128, GSMEM>>>(
        gA_p, gBq_p, bqkv, nullptr, QKVN, q_p, k_p, v_p);

    // 2) causal flash attention; epilogue writes proj-input triplets into gA
    attn_mma<<<dim3(T_ / 64, B_ * H_), 128, ATTN_SMEM>>>(q_p, k_p, v_p, gA_p);

    // 3) output projection
    gemm_tc<0><<<dim3(C_ / 128, M_ / 128), 128, GSMEM>>>(
        gA_p, gBp_p, bproj, out, C_, nullptr, nullptr, nullptr);
}

// round 9
// speedup vs baseline: 2.9923x; 1.1168x over previous
#include <cuda_runtime.h>
#include <cuda_bf16.h>
#include <cstdint>
#include <math.h>

#define B_    2
#define T_    2048
#define C_    1024
#define H_    16
#define D_    64
#define M_    4096
#define QKVN  3072
#define KB_   3072            // expanded bf16 K (3 * 1024)
#define NIT   48              // k-iterations of BK=64 expanded bf16

// ---- scratch (__device__ globals) ------------------------------------------
// Tiled+swizzled layouts: [tile][kstage 0..47][row 0..127][128B, chunk^=(row&7)]
__device__ __nv_bfloat16 gA[M_ * KB_];             // 24 MB activations (tiled)
__device__ __nv_bfloat16 gBq[QKVN * (size_t)KB_];  // 18 MB W_qkv^T (tiled)
__device__ __nv_bfloat16 gBp[C_ * (size_t)KB_];    // 6 MB  W_proj^T (tiled)
// per-(b,h) hi/lo split q,k,v: [bh][T][128] (linear, unchanged)
__device__ __nv_bfloat16 gQsp[B_ * H_ * T_ * 128];
__device__ __nv_bfloat16 gKsp[B_ * H_ * T_ * 128];
__device__ __nv_bfloat16 gVsp[B_ * H_ * T_ * 128];

// ============================================================================
// PTX helpers
// ============================================================================
__device__ __forceinline__ uint32_t smem_u32(const void* p) {
    uint32_t a;
    asm("{ .reg .u64 t; cvta.to.shared.u64 t, %1; cvt.u32.u64 %0, t; }" : "=r"(a) : "l"(p));
    return a;
}
__device__ __forceinline__ void cp16(uint32_t dst, const void* src) {
    asm volatile("cp.async.cg.shared.global [%0], [%1], 16;" :: "r"(dst), "l"(src));
}
#define CP_COMMIT() asm volatile("cp.async.commit_group;" ::: "memory")
#define CP_WAIT0()  asm volatile("cp.async.wait_group 0;" ::: "memory")

__device__ __forceinline__ void bulk_cp(uint32_t dst, const void* src, uint32_t bytes,
                                        uint32_t mbar) {
    asm volatile(
        "cp.async.bulk.shared::cluster.global.mbarrier::complete_tx::bytes [%0], [%1], %2, [%3];"
        :: "r"(dst), "l"(src), "r"(bytes), "r"(mbar) : "memory");
}
#define MBAR_INIT(mbar, cnt)  asm volatile("mbarrier.init.shared.b64 [%0], %1;" :: "r"((uint32_t)(mbar)), "r"((uint32_t)(cnt)) : "memory")
#define MBAR_EXPECT_TX(mbar, bytes) asm volatile("mbarrier.arrive.expect_tx.shared.b64 _, [%0], %1;" :: "r"((uint32_t)(mbar)), "r"((uint32_t)(bytes)) : "memory")
#define MBAR_WAIT(mbar, parity) do {                                            \
    uint32_t _m = (uint32_t)(mbar); uint32_t _p = (uint32_t)(parity);           \
    asm volatile("{\n\t.reg .pred P1;\n\t"                                      \
        "WAIT_LOOP_%=:\n\t"                                                     \
        "mbarrier.try_wait.parity.acquire.cta.shared::cta.b64 P1, [%0], %1, 0x989680;\n\t" \
        "@P1 bra.uni WAIT_DONE_%=;\n\t"                                         \
        "bra.uni WAIT_LOOP_%=;\n\t"                                             \
        "WAIT_DONE_%=:\n\t}" :: "r"(_m), "r"(_p) : "memory");                   \
} while (0)

__device__ __forceinline__ void ldm4(uint32_t* r, uint32_t addr) {
    asm volatile("ldmatrix.sync.aligned.m8n8.x4.shared.b16 {%0,%1,%2,%3}, [%4];"
        : "=r"(r[0]), "=r"(r[1]), "=r"(r[2]), "=r"(r[3]) : "r"(addr));
}
__device__ __forceinline__ void ldm4t(uint32_t* r, uint32_t addr) {
    asm volatile("ldmatrix.sync.aligned.m8n8.x4.trans.shared.b16 {%0,%1,%2,%3}, [%4];"
        : "=r"(r[0]), "=r"(r[1]), "=r"(r[2]), "=r"(r[3]) : "r"(addr));
}
__device__ __forceinline__ void mma16816(float* c, const uint32_t* a, const uint32_t* b) {
    asm volatile(
        "mma.sync.aligned.m16n8k16.row.col.f32.bf16.bf16.f32 "
        "{%0,%1,%2,%3}, {%4,%5,%6,%7}, {%8,%9}, {%0,%1,%2,%3};"
        : "+f"(c[0]), "+f"(c[1]), "+f"(c[2]), "+f"(c[3])
        : "r"(a[0]), "r"(a[1]), "r"(a[2]), "r"(a[3]), "r"(b[0]), "r"(b[1]));
}
__device__ __forceinline__ uint32_t pack_bf2(__nv_bfloat16 lo, __nv_bfloat16 hi) {
    return ((uint32_t)__bfloat16_as_ushort(hi) << 16) | (uint32_t)__bfloat16_as_ushort(lo);
}

// ============================================================================
// Conversion kernels -> tiled+swizzled layouts
// ============================================================================
// fp32 x -> [hi,hi,lo] triplets, tiled-swizzled
__global__ __launch_bounds__(256) void convert_act(const float* __restrict__ x,
                                                   __nv_bfloat16* __restrict__ A) {
    int idx = blockIdx.x * 256 + threadIdx.x;
    int m  = idx >> 7;
    int kg = idx & 127;
    const float* p = x + (size_t)m * C_ + kg * 8;
    float4 v0 = *(const float4*)p;
    float4 v1 = *(const float4*)(p + 4);
    float v[8] = {v0.x, v0.y, v0.z, v0.w, v1.x, v1.y, v1.z, v1.w};
    union { __nv_bfloat16 h[24]; uint4 u[3]; } o;
    #pragma unroll
    for (int j = 0; j < 8; j++) {
        __nv_bfloat16 hi = __float2bfloat16(v[j]);
        __nv_bfloat16 lo = __float2bfloat16(v[j] - __bfloat162float(hi));
        o.h[3*j + 0] = hi; o.h[3*j + 1] = hi; o.h[3*j + 2] = lo;
    }
    char* base = (char*)A;
    #pragma unroll
    for (int j = 0; j < 3; j++) {
        int gc = kg * 3 + j;
        int st = gc >> 3;
        int pc = (gc & 7) ^ (m & 7);
        *(uint4*)(base + (((size_t)(m >> 7) * NIT + st) << 14)
                       + (m & 127) * 128 + pc * 16) = o.u[j];
    }
}

// W[K][N] fp32 -> tiled-swizzled [hi,lo,hi]
__global__ __launch_bounds__(128) void convert_w(const float* __restrict__ W,
                                                 __nv_bfloat16* __restrict__ Wp, int N) {
    __shared__ float s[32][33];
    int n0 = blockIdx.x * 32;
    int t = threadIdx.x;
    {
        int kr = t >> 3, nc = (t & 7) * 4;
        #pragma unroll
        for (int i = 0; i < 2; i++) {
            int k = kr + i * 16;
            float4 v = *(const float4*)(W + (size_t)(blockIdx.y * 32 + k) * N + n0 + nc);
            s[k][nc] = v.x; s[k][nc+1] = v.y; s[k][nc+2] = v.z; s[k][nc+3] = v.w;
        }
    }
    __syncthreads();
    int nl = t >> 2, kg = t & 3;
    union { __nv_bfloat16 h[24]; uint4 u[3]; } o;
    #pragma unroll
    for (int j = 0; j < 8; j++) {
        float v = s[kg * 8 + j][nl];
        __nv_bfloat16 hi = __float2bfloat16(v);
        __nv_bfloat16 lo = __float2bfloat16(v - __bfloat162float(hi));
        o.h[3*j + 0] = hi; o.h[3*j + 1] = lo; o.h[3*j + 2] = hi;
    }
    int n = n0 + nl;
    char* base = (char*)Wp;
    #pragma unroll
    for (int j = 0; j < 3; j++) {
        int gc = blockIdx.y * 12 + kg * 3 + j;
        int st = gc >> 3;
        int pc = (gc & 7) ^ (n & 7);
        *(uint4*)(base + (((size_t)(n >> 7) * NIT + st) << 14)
                       + (n & 127) * 128 + pc * 16) = o.u[j];
    }
}

// ============================================================================
// HMMA GEMM: CTA 128x128, 4 warps 64x64, BK=64, 3-stage cp.async.bulk ring.
// Operands in tiled-swizzled gmem; one elected thread issues 2 bulk copies.
// MODE 0: fp32 out + bias. MODE 1: hi/lo-split q/k/v epilogue.
// ============================================================================
#define STAGEB 32768
#define GSMEM  (3 * STAGEB + 64)   // 98368

template <int MODE>
__global__ __launch_bounds__(128, 2) void gemm_tc(
    const __nv_bfloat16* __restrict__ A, const __nv_bfloat16* __restrict__ Bw,
    const float* __restrict__ bias, float* __restrict__ Co, int Ntot,
    __nv_bfloat16* __restrict__ Qs, __nv_bfloat16* __restrict__ Ks,
    __nv_bfloat16* __restrict__ Vs)
{
    extern __shared__ char smemraw[];
    const uint32_t sb = smem_u32(smemraw);
    const uint32_t mb = sb + 3 * STAGEB;

    const int tid  = threadIdx.x;
    const int lane = tid & 31;
    const int wid  = tid >> 5;
    const int wr   = wid >> 1;
    const int wc   = wid & 1;

    const char* Ag = (const char*)A + ((size_t)blockIdx.y * NIT << 14);
    const char* Bg = (const char*)Bw + ((size_t)blockIdx.x * NIT << 14);

    if (tid == 0) {
        MBAR_INIT(mb + 0, 1); MBAR_INIT(mb + 8, 1); MBAR_INIT(mb + 16, 1);
    }
    __syncthreads();

    auto issue = [&](int s) {
        if (tid == 0) {
            int buf = s % 3;
            uint32_t mbar = mb + (uint32_t)buf * 8;
            uint32_t dA = sb + (uint32_t)buf * STAGEB;
            MBAR_EXPECT_TX(mbar, 32768);
            bulk_cp(dA,          Ag + ((size_t)s << 14), 16384, mbar);
            bulk_cp(dA + 16384u, Bg + ((size_t)s << 14), 16384, mbar);
        }
    };
    issue(0); issue(1); issue(2);

    float acc[4][8][4];
    #pragma unroll
    for (int mt = 0; mt < 4; mt++)
        #pragma unroll
        for (int nt = 0; nt < 8; nt++)
            #pragma unroll
            for (int q = 0; q < 4; q++) acc[mt][nt][q] = 0.f;

    const int arow = (lane & 7) + ((lane >> 3) & 1) * 8;
    const int achk = lane >> 4;
    const int brw  = (lane & 7) + ((lane >> 4) & 1) * 8;
    const int bchk = (lane >> 3) & 1;
    const int xa = arow & 7, xb = brw & 7;

    #pragma unroll 1
    for (int s = 0; s < NIT; s++) {
        const int buf = s % 3;
        MBAR_WAIT(mb + (uint32_t)buf * 8, (s / 3) & 1);
        const uint32_t bA = sb + (uint32_t)buf * STAGEB;
        const uint32_t bB = bA + 16384u;

        #pragma unroll
        for (int ks = 0; ks < 4; ks++) {
            uint32_t afr[4][4], bfr[4][4];
            const int ca = ((2 * ks + achk) ^ xa) * 16;
            const int cb = ((2 * ks + bchk) ^ xb) * 16;
            #pragma unroll
            for (int mt = 0; mt < 4; mt++)
                ldm4(afr[mt], bA + (uint32_t)((wr * 64 + mt * 16 + arow) * 128 + ca));
            #pragma unroll
            for (int n2 = 0; n2 < 4; n2++)
                ldm4(bfr[n2], bB + (uint32_t)((wc * 64 + n2 * 16 + brw) * 128 + cb));
            #pragma unroll
            for (int mt = 0; mt < 4; mt++)
                #pragma unroll
                for (int nt = 0; nt < 8; nt++)
                    mma16816(acc[mt][nt], afr[mt], &bfr[nt >> 1][(nt & 1) * 2]);
        }
        __syncthreads();
        if (s + 3 < NIT) issue(s + 3);
    }

    const int brow = blockIdx.y * 128;
    const int bcol = blockIdx.x * 128;
    const int crow = lane >> 2;
    const int ccol = (lane & 3) * 2;

    if (MODE == 0) {
        #pragma unroll
        for (int nt = 0; nt < 8; nt++) {
            int col = bcol + wc * 64 + nt * 8 + ccol;
            float2 bi = *(const float2*)(bias + col);
            #pragma unroll
            for (int mt = 0; mt < 4; mt++) {
                int row = brow + wr * 64 + mt * 16 + crow;
                float2 v0 = make_float2(acc[mt][nt][0] + bi.x, acc[mt][nt][1] + bi.y);
                float2 v1 = make_float2(acc[mt][nt][2] + bi.x, acc[mt][nt][3] + bi.y);
                *(float2*)(Co + (size_t)row * Ntot + col)       = v0;
                *(float2*)(Co + (size_t)(row + 8) * Ntot + col) = v1;
            }
        }
    } else {
        const int p  = bcol >> 10;
        __nv_bfloat16* outb = (p == 0) ? Qs : ((p == 1) ? Ks : Vs);
        const float sc = (p == 0) ? 0.125f : 1.f;
        const int hh = ((bcol + wc * 64) >> 6) & 15;
        #pragma unroll
        for (int nt = 0; nt < 8; nt++) {
            int gcol = bcol + wc * 64 + nt * 8 + ccol;
            float2 bi = *(const float2*)(bias + gcol);
            int d = nt * 8 + ccol;
            #pragma unroll
            for (int mt = 0; mt < 4; mt++) {
                int grow = brow + wr * 64 + mt * 16 + crow;
                #pragma unroll
                for (int half = 0; half < 2; half++) {
                    int m = grow + half * 8;
                    int bb = m >> 11, t = m & 2047;
                    float f0 = (acc[mt][nt][half * 2 + 0] + bi.x) * sc;
                    float f1 = (acc[mt][nt][half * 2 + 1] + bi.y) * sc;
                    __nv_bfloat16 h0 = __float2bfloat16(f0);
                    __nv_bfloat16 l0 = __float2bfloat16(f0 - __bfloat162float(h0));
                    __nv_bfloat16 h1 = __float2bfloat16(f1);
                    __nv_bfloat16 l1 = __float2bfloat16(f1 - __bfloat162float(h1));
                    char* row = (char*)(outb + (((size_t)(bb * H_ + hh) * T_) + t) * 128);
                    *(uint32_t*)(row + 2 * d)       = pack_bf2(h0, h1);
                    *(uint32_t*)(row + 128 + 2 * d) = pack_bf2(l0, l1);
                }
            }
        }
    }
}

// ============================================================================
// HMMA flash attention (R7 design); epilogue writes tiled-swizzled gA.
// ============================================================================
#define ASTR  272
#define ATILE (64 * ASTR)
#define ATTN_SMEM (6 * ATILE)   // 104448 B

__global__ __launch_bounds__(128, 2) void attn_mma(
    const __nv_bfloat16* __restrict__ Qsp, const __nv_bfloat16* __restrict__ Ksp,
    const __nv_bfloat16* __restrict__ Vsp, __nv_bfloat16* __restrict__ Aout)
{
    extern __shared__ char smbuf[];
    const uint32_t sb   = smem_u32(smbuf);
    const uint32_t qs_b = sb;
    const uint32_t ps_b = sb + 5 * ATILE;
    char* Psc = smbuf + 5 * ATILE;

    const int tid  = threadIdx.x;
    const int lane = tid & 31;
    const int wid  = tid >> 5;
    const int qt   = (int)gridDim.x - 1 - (int)blockIdx.x;
    const int bh   = blockIdx.y;
    const int b = bh >> 4, h = bh & 15;

    const __nv_bfloat16* Qg = Qsp + ((size_t)bh * T_ + qt * 64) * 128;
    const __nv_bfloat16* Kg = Ksp + (size_t)bh * T_ * 128;
    const __nv_bfloat16* Vg = Vsp + (size_t)bh * T_ * 128;

    auto stage64 = [&](uint32_t sm, const __nv_bfloat16* g) {
        const char* gc = (const char*)g;
        #pragma unroll
        for (int i = 0; i < 8; i++) {
            int c = tid + 128 * i;
            cp16(sm + (uint32_t)((c >> 4) * ASTR + (c & 15) * 16),
                 gc + (c >> 4) * 256 + (c & 15) * 16);
        }
    };

    const int arow = (lane & 7) + ((lane >> 3) & 1) * 8;
    const int achk = lane >> 4;
    const uint32_t aoff = (uint32_t)((wid * 16 + arow) * ASTR + achk * 16);
    const int brw  = (lane & 7) + ((lane >> 4) & 1) * 8;
    const int bchk = (lane >> 3) & 1;
    uint32_t boffs[4];
    #pragma unroll
    for (int n2 = 0; n2 < 4; n2++)
        boffs[n2] = (uint32_t)((n2 * 16 + brw) * ASTR + bchk * 16);
    const uint32_t voff = (uint32_t)(arow * ASTR + achk * 16);

    stage64(qs_b, Qg);
    stage64(sb + 1 * ATILE, Kg);
    stage64(sb + 2 * ATILE, Vg);
    CP_COMMIT();

    float m0 = -1e30f, m1 = -1e30f, l0 = 0.f, l1 = 0.f;
    float accO[8][4];
    #pragma unroll
    for (int nt = 0; nt < 8; nt++)
        #pragma unroll
        for (int q = 0; q < 4; q++) accO[nt][q] = 0.f;

    const int r0 = lane >> 2;
    const int c0 = (lane & 3) * 2;
    const int row0 = wid * 16 + r0;

    #pragma unroll 1
    for (int kt = 0; kt <= qt; kt++) {
        CP_WAIT0();
        __syncthreads();
        const uint32_t kbuf = sb + (uint32_t)(1 + 2 * (kt & 1)) * ATILE;
        const uint32_t vbuf = kbuf + ATILE;

        if (kt < qt) {
            uint32_t nb = sb + (uint32_t)(1 + 2 * ((kt + 1) & 1)) * ATILE;
            stage64(nb,         Kg + (size_t)(kt + 1) * 64 * 128);
            stage64(nb + ATILE, Vg + (size_t)(kt + 1) * 64 * 128);
        }
        CP_COMMIT();

        float accS[8][4];
        #pragma unroll
        for (int nt = 0; nt < 8; nt++)
            #pragma unroll
            for (int q = 0; q < 4; q++) accS[nt][q] = 0.f;
        #pragma unroll
        for (int pass = 0; pass < 3; pass++) {
            uint32_t aadd = (pass == 2) ? 128u : 0u;
            uint32_t badd = (pass == 1) ? 128u : 0u;
            #pragma unroll
            for (int ks = 0; ks < 4; ks++) {
                uint32_t afr[4], bfr[4][4];
                ldm4(afr, qs_b + aoff + aadd + ks * 32);
                #pragma unroll
                for (int n2 = 0; n2 < 4; n2++)
                    ldm4(bfr[n2], kbuf + boffs[n2] + badd + ks * 32);
                #pragma unroll
                for (int nt = 0; nt < 8; nt++)
                    mma16816(accS[nt], afr, &bfr[nt >> 1][(nt & 1) * 2]);
            }
        }

        if (kt == qt) {
            #pragma unroll
            for (int nt = 0; nt < 8; nt++) {
                int col = nt * 8 + c0;
                if (col     > row0)     accS[nt][0] = -1e30f;
                if (col + 1 > row0)     accS[nt][1] = -1e30f;
                if (col     > row0 + 8) accS[nt][2] = -1e30f;
                if (col + 1 > row0 + 8) accS[nt][3] = -1e30f;
            }
        }

        {
            float mx0 = -1e30f, mx1 = -1e30f;
            #pragma unroll
            for (int nt = 0; nt < 8; nt++) {
                mx0 = fmaxf(mx0, fmaxf(accS[nt][0], accS[nt][1]));
                mx1 = fmaxf(mx1, fmaxf(accS[nt][2], accS[nt][3]));
            }
            mx0 = fmaxf(mx0, __shfl_xor_sync(0xffffffffu, mx0, 1));
            mx0 = fmaxf(mx0, __shfl_xor_sync(0xffffffffu, mx0, 2));
            mx1 = fmaxf(mx1, __shfl_xor_sync(0xffffffffu, mx1, 1));
            mx1 = fmaxf(mx1, __shfl_xor_sync(0xffffffffu, mx1, 2));

            float mn0 = fmaxf(m0, mx0), mn1 = fmaxf(m1, mx1);
            float al0 = __expf(m0 - mn0), al1 = __expf(m1 - mn1);
            m0 = mn0; m1 = mn1;

            char* prow0 = Psc + (wid * 16 + r0) * ASTR + c0 * 2;
            char* prow1 = prow0 + 8 * ASTR;
            float sum0 = 0.f, sum1 = 0.f;
            #pragma unroll
            for (int nt = 0; nt < 8; nt++) {
                float p0 = __expf(accS[nt][0] - mn0);
                float p1 = __expf(accS[nt][1] - mn0);
                float p2 = __expf(accS[nt][2] - mn1);
                float p3 = __expf(accS[nt][3] - mn1);
                sum0 += p0 + p1; sum1 += p2 + p3;
                __nv_bfloat16 h0 = __float2bfloat16(p0), h1 = __float2bfloat16(p1);
                __nv_bfloat16 h2 = __float2bfloat16(p2), h3 = __float2bfloat16(p3);
                __nv_bfloat16 g0 = __float2bfloat16(p0 - __bfloat162float(h0));
                __nv_bfloat16 g1 = __float2bfloat16(p1 - __bfloat162float(h1));
                __nv_bfloat16 g2 = __float2bfloat16(p2 - __bfloat162float(h2));
                __nv_bfloat16 g3 = __float2bfloat16(p3 - __bfloat162float(h3));
                *(uint32_t*)(prow0 + nt * 16)        = pack_bf2(h0, h1);
                *(uint32_t*)(prow0 + 128 + nt * 16)  = pack_bf2(g0, g1);
                *(uint32_t*)(prow1 + nt * 16)        = pack_bf2(h2, h3);
                *(uint32_t*)(prow1 + 128 + nt * 16)  = pack_bf2(g2, g3);
            }
            sum0 += __shfl_xor_sync(0xffffffffu, sum0, 1);
            sum0 += __shfl_xor_sync(0xffffffffu, sum0, 2);
            sum1 += __shfl_xor_sync(0xffffffffu, sum1, 1);
            sum1 += __shfl_xor_sync(0xffffffffu, sum1, 2);
            l0 = l0 * al0 + sum0;
            l1 = l1 * al1 + sum1;

            #pragma unroll
            for (int nt = 0; nt < 8; nt++) {
                accO[nt][0] *= al0; accO[nt][1] *= al0;
                accO[nt][2] *= al1; accO[nt][3] *= al1;
            }
        }
        __syncwarp();

        #pragma unroll
        for (int pass = 0; pass < 3; pass++) {
            uint32_t aadd = (pass == 2) ? 128u : 0u;
            uint32_t badd = (pass == 1) ? 128u : 0u;
            #pragma unroll
            for (int ks = 0; ks < 4; ks++) {
                uint32_t pfr[4], vfr[4][4];
                ldm4(pfr, ps_b + aoff + aadd + ks * 32);
                #pragma unroll
                for (int n2 = 0; n2 < 4; n2++)
                    ldm4t(vfr[n2], vbuf + (uint32_t)(ks * 16 * ASTR) + voff + n2 * 32 + badd);
                #pragma unroll
                for (int nt = 0; nt < 8; nt++)
                    mma16816(accO[nt], pfr, &vfr[nt >> 1][(nt & 1) * 2]);
            }
        }
        __syncwarp();
    }

    // ---- normalize + write [hi,hi,lo] triplets into TILED-SWIZZLED gA
    float inv0 = 1.f / l0, inv1 = 1.f / l1;
    int grow = qt * 64 + wid * 16 + r0;
    size_t m0r = (size_t)b * T_ + grow;
    size_t m1r = m0r + 8;
    char* Ac = (char*)Aout;
    auto writeWord = [&](size_t m, int o, uint32_t val) {
        int gc = o >> 4, st = gc >> 3, pc = (gc & 7) ^ ((int)m & 7);
        *(uint32_t*)(Ac + (((m >> 7) * NIT + st) << 14)
                        + (m & 127) * 128 + pc * 16 + (o & 15)) = val;
    };
    #pragma unroll
    for (int nt = 0; nt < 8; nt++) {
        int d = nt * 8 + c0;
        int o = (h * D_ + d) * 6;
        float f0 = accO[nt][0] * inv0, f1 = accO[nt][1] * inv0;
        float f2 = accO[nt][2] * inv1, f3 = accO[nt][3] * inv1;
        __nv_bfloat16 h0 = __float2bfloat16(f0);
        __nv_bfloat16 e0 = __float2bfloat16(f0 - __bfloat162float(h0));
        __nv_bfloat16 h1 = __float2bfloat16(f1);
        __nv_bfloat16 e1 = __float2bfloat16(f1 - __bfloat162float(h1));
        __nv_bfloat16 h2 = __float2bfloat16(f2);
        __nv_bfloat16 e2 = __float2bfloat16(f2 - __bfloat162float(h2));
        __nv_bfloat16 h3 = __float2bfloat16(f3);
        __nv_bfloat16 e3 = __float2bfloat16(f3 - __bfloat162float(h3));
        writeWord(m0r, o + 0, pack_bf2(h0, h0));
        writeWord(m0r, o + 4, pack_bf2(e0, h1));
        writeWord(m0r, o + 8, pack_bf2(h1, e1));
        writeWord(m1r, o + 0, pack_bf2(h2, h2));
        writeWord(m1r, o + 4, pack_bf2(e2, h3));
        writeWord(m1r, o + 8, pack_bf2(h3, e3));
    }
}

// ---------------------------------------------------------------------------
extern "C" void kernel_launch(void* const* d_in, const int* in_sizes, int n_in,
                              void* d_out, int out_size)
{
    const float* x     = (const float*)d_in[0];
    const float* Wqkv  = (const float*)d_in[1];
    const float* bqkv  = (const float*)d_in[2];
    const float* Wproj = (const float*)d_in[3];
    const float* bproj = (const float*)d_in[4];
    float* out = (float*)d_out;

    __nv_bfloat16 *gA_p = nullptr, *gBq_p = nullptr, *gBp_p = nullptr;
    __nv_bfloat16 *q_p = nullptr, *k_p = nullptr, *v_p = nullptr;
    cudaGetSymbolAddress((void**)&gA_p,  gA);
    cudaGetSymbolAddress((void**)&gBq_p, gBq);
    cudaGetSymbolAddress((void**)&gBp_p, gBp);
    cudaGetSymbolAddress((void**)&q_p,   gQsp);
    cudaGetSymbolAddress((void**)&k_p,   gKsp);
    cudaGetSymbolAddress((void**)&v_p,   gVsp);

    cudaFuncSetAttribute(attn_mma,
                         cudaFuncAttributeMaxDynamicSharedMemorySize, ATTN_SMEM);
    cudaFuncSetAttribute(gemm_tc<0>,
                         cudaFuncAttributeMaxDynamicSharedMemorySize, GSMEM);
    cudaFuncSetAttribute(gemm_tc<1>,
                         cudaFuncAttributeMaxDynamicSharedMemorySize, GSMEM);

    // conversions (tiled+swizzled outputs)
    convert_w<<<dim3(QKVN / 32, C_ / 32), 128>>>(Wqkv, gBq_p, QKVN);
    convert_w<<<dim3(C_ / 32, C_ / 32), 128>>>(Wproj, gBp_p, C_);
    convert_act<<<(M_ * C_ / 8) / 256, 256>>>(x, gA_p);

    // 1) QKV projection, fused split-qkv epilogue
    gemm_tc<1><<<dim3(QKVN / 128, M_ / 128), 128, GSMEM>>>(
        gA_p, gBq_p, bqkv, nullptr, QKVN, q_p, k_p, v_p);

    // 2) causal flash attention; epilogue writes proj-input triplets into gA
    attn_mma<<<dim3(T_ / 64, B_ * H_), 128, ATTN_SMEM>>>(q_p, k_p, v_p, gA_p);

    // 3) output projection
    gemm_tc<0><<<dim3(C_ / 128, M_ / 128), 128, GSMEM>>>(
        gA_p, gBp_p, bproj, out, C_, nullptr, nullptr, nullptr);
}

// round 10
// speedup vs baseline: 3.0842x; 1.0307x over previous
#include <cuda_runtime.h>
#include <cuda_bf16.h>
#include <cstdint>
#include <math.h>

#define B_    2
#define T_    2048
#define C_    1024
#define H_    16
#define D_    64
#define M_    4096
#define QKVN  3072
#define KB_   3072            // expanded bf16 K (3 * 1024)
#define NIT   48              // k-iterations of BK=64 expanded bf16

// ---- scratch (__device__ globals) ------------------------------------------
// GEMM operands, tiled+swizzled: [tile][kstage][row 0..127][128B, chunk^=(row&7)]
__device__ __nv_bfloat16 gA[M_ * KB_];             // 24 MB activations
__device__ __nv_bfloat16 gBq[QKVN * (size_t)KB_];  // 18 MB W_qkv^T
__device__ __nv_bfloat16 gBp[C_ * (size_t)KB_];    // 6 MB  W_proj^T
// q/k/v, per-(bh, 64-token tile) contiguous 16KB blocks:
// [bh][tile][token 0..63][256B = hi(128)|lo(128), chunk^=(token&7)]
__device__ __nv_bfloat16 gQsp[B_ * H_ * T_ * 128];
__device__ __nv_bfloat16 gKsp[B_ * H_ * T_ * 128];
__device__ __nv_bfloat16 gVsp[B_ * H_ * T_ * 128];

// ============================================================================
// PTX helpers
// ============================================================================
__device__ __forceinline__ uint32_t smem_u32(const void* p) {
    uint32_t a;
    asm("{ .reg .u64 t; cvta.to.shared.u64 t, %1; cvt.u32.u64 %0, t; }" : "=r"(a) : "l"(p));
    return a;
}
__device__ __forceinline__ void bulk_cp(uint32_t dst, const void* src, uint32_t bytes,
                                        uint32_t mbar) {
    asm volatile(
        "cp.async.bulk.shared::cluster.global.mbarrier::complete_tx::bytes [%0], [%1], %2, [%3];"
        :: "r"(dst), "l"(src), "r"(bytes), "r"(mbar) : "memory");
}
#define MBAR_INIT(mbar, cnt)  asm volatile("mbarrier.init.shared.b64 [%0], %1;" :: "r"((uint32_t)(mbar)), "r"((uint32_t)(cnt)) : "memory")
#define MBAR_EXPECT_TX(mbar, bytes) asm volatile("mbarrier.arrive.expect_tx.shared.b64 _, [%0], %1;" :: "r"((uint32_t)(mbar)), "r"((uint32_t)(bytes)) : "memory")
#define MBAR_WAIT(mbar, parity) do {                                            \
    uint32_t _m = (uint32_t)(mbar); uint32_t _p = (uint32_t)(parity);           \
    asm volatile("{\n\t.reg .pred P1;\n\t"                                      \
        "WAIT_LOOP_%=:\n\t"                                                     \
        "mbarrier.try_wait.parity.acquire.cta.shared::cta.b64 P1, [%0], %1, 0x989680;\n\t" \
        "@P1 bra.uni WAIT_DONE_%=;\n\t"                                         \
        "bra.uni WAIT_LOOP_%=;\n\t"                                             \
        "WAIT_DONE_%=:\n\t}" :: "r"(_m), "r"(_p) : "memory");                   \
} while (0)

__device__ __forceinline__ void ldm4(uint32_t* r, uint32_t addr) {
    asm volatile("ldmatrix.sync.aligned.m8n8.x4.shared.b16 {%0,%1,%2,%3}, [%4];"
        : "=r"(r[0]), "=r"(r[1]), "=r"(r[2]), "=r"(r[3]) : "r"(addr));
}
__device__ __forceinline__ void ldm4t(uint32_t* r, uint32_t addr) {
    asm volatile("ldmatrix.sync.aligned.m8n8.x4.trans.shared.b16 {%0,%1,%2,%3}, [%4];"
        : "=r"(r[0]), "=r"(r[1]), "=r"(r[2]), "=r"(r[3]) : "r"(addr));
}
__device__ __forceinline__ void mma16816(float* c, const uint32_t* a, const uint32_t* b) {
    asm volatile(
        "mma.sync.aligned.m16n8k16.row.col.f32.bf16.bf16.f32 "
        "{%0,%1,%2,%3}, {%4,%5,%6,%7}, {%8,%9}, {%0,%1,%2,%3};"
        : "+f"(c[0]), "+f"(c[1]), "+f"(c[2]), "+f"(c[3])
        : "r"(a[0]), "r"(a[1]), "r"(a[2]), "r"(a[3]), "r"(b[0]), "r"(b[1]));
}
__device__ __forceinline__ uint32_t pack_bf2(__nv_bfloat16 lo, __nv_bfloat16 hi) {
    return ((uint32_t)__bfloat16_as_ushort(hi) << 16) | (uint32_t)__bfloat16_as_ushort(lo);
}

// ============================================================================
// Conversion kernels -> tiled+swizzled GEMM layouts (unchanged from R9)
// ============================================================================
__global__ __launch_bounds__(256) void convert_act(const float* __restrict__ x,
                                                   __nv_bfloat16* __restrict__ A) {
    int idx = blockIdx.x * 256 + threadIdx.x;
    int m  = idx >> 7;
    int kg = idx & 127;
    const float* p = x + (size_t)m * C_ + kg * 8;
    float4 v0 = *(const float4*)p;
    float4 v1 = *(const float4*)(p + 4);
    float v[8] = {v0.x, v0.y, v0.z, v0.w, v1.x, v1.y, v1.z, v1.w};
    union { __nv_bfloat16 h[24]; uint4 u[3]; } o;
    #pragma unroll
    for (int j = 0; j < 8; j++) {
        __nv_bfloat16 hi = __float2bfloat16(v[j]);
        __nv_bfloat16 lo = __float2bfloat16(v[j] - __bfloat162float(hi));
        o.h[3*j + 0] = hi; o.h[3*j + 1] = hi; o.h[3*j + 2] = lo;
    }
    char* base = (char*)A;
    #pragma unroll
    for (int j = 0; j < 3; j++) {
        int gc = kg * 3 + j;
        int st = gc >> 3;
        int pc = (gc & 7) ^ (m & 7);
        *(uint4*)(base + (((size_t)(m >> 7) * NIT + st) << 14)
                       + (m & 127) * 128 + pc * 16) = o.u[j];
    }
}

__global__ __launch_bounds__(128) void convert_w(const float* __restrict__ W,
                                                 __nv_bfloat16* __restrict__ Wp, int N) {
    __shared__ float s[32][33];
    int n0 = blockIdx.x * 32;
    int t = threadIdx.x;
    {
        int kr = t >> 3, nc = (t & 7) * 4;
        #pragma unroll
        for (int i = 0; i < 2; i++) {
            int k = kr + i * 16;
            float4 v = *(const float4*)(W + (size_t)(blockIdx.y * 32 + k) * N + n0 + nc);
            s[k][nc] = v.x; s[k][nc+1] = v.y; s[k][nc+2] = v.z; s[k][nc+3] = v.w;
        }
    }
    __syncthreads();
    int nl = t >> 2, kg = t & 3;
    union { __nv_bfloat16 h[24]; uint4 u[3]; } o;
    #pragma unroll
    for (int j = 0; j < 8; j++) {
        float v = s[kg * 8 + j][nl];
        __nv_bfloat16 hi = __float2bfloat16(v);
        __nv_bfloat16 lo = __float2bfloat16(v - __bfloat162float(hi));
        o.h[3*j + 0] = hi; o.h[3*j + 1] = lo; o.h[3*j + 2] = hi;
    }
    int n = n0 + nl;
    char* base = (char*)Wp;
    #pragma unroll
    for (int j = 0; j < 3; j++) {
        int gc = blockIdx.y * 12 + kg * 3 + j;
        int st = gc >> 3;
        int pc = (gc & 7) ^ (n & 7);
        *(uint4*)(base + (((size_t)(n >> 7) * NIT + st) << 14)
                       + (n & 127) * 128 + pc * 16) = o.u[j];
    }
}

// ============================================================================
// HMMA GEMM (R9 design): CTA 128x128, 4 warps 64x64, BK=64, bulk-copy ring.
// MODE 0: fp32 out + bias. MODE 1: writes swizzled q/k/v attention tiles.
// ============================================================================
#define STAGEB 32768
#define GSMEM  (3 * STAGEB + 64)   // 98368

template <int MODE>
__global__ __launch_bounds__(128, 2) void gemm_tc(
    const __nv_bfloat16* __restrict__ A, const __nv_bfloat16* __restrict__ Bw,
    const float* __restrict__ bias, float* __restrict__ Co, int Ntot,
    __nv_bfloat16* __restrict__ Qs, __nv_bfloat16* __restrict__ Ks,
    __nv_bfloat16* __restrict__ Vs)
{
    extern __shared__ char smemraw[];
    const uint32_t sb = smem_u32(smemraw);
    const uint32_t mb = sb + 3 * STAGEB;

    const int tid  = threadIdx.x;
    const int lane = tid & 31;
    const int wid  = tid >> 5;
    const int wr   = wid >> 1;
    const int wc   = wid & 1;

    const char* Ag = (const char*)A + ((size_t)blockIdx.y * NIT << 14);
    const char* Bg = (const char*)Bw + ((size_t)blockIdx.x * NIT << 14);

    if (tid == 0) {
        MBAR_INIT(mb + 0, 1); MBAR_INIT(mb + 8, 1); MBAR_INIT(mb + 16, 1);
    }
    __syncthreads();

    auto issue = [&](int s) {
        if (tid == 0) {
            int buf = s % 3;
            uint32_t mbar = mb + (uint32_t)buf * 8;
            uint32_t dA = sb + (uint32_t)buf * STAGEB;
            MBAR_EXPECT_TX(mbar, 32768);
            bulk_cp(dA,          Ag + ((size_t)s << 14), 16384, mbar);
            bulk_cp(dA + 16384u, Bg + ((size_t)s << 14), 16384, mbar);
        }
    };
    issue(0); issue(1); issue(2);

    float acc[4][8][4];
    #pragma unroll
    for (int mt = 0; mt < 4; mt++)
        #pragma unroll
        for (int nt = 0; nt < 8; nt++)
            #pragma unroll
            for (int q = 0; q < 4; q++) acc[mt][nt][q] = 0.f;

    const int arow = (lane & 7) + ((lane >> 3) & 1) * 8;
    const int achk = lane >> 4;
    const int brw  = (lane & 7) + ((lane >> 4) & 1) * 8;
    const int bchk = (lane >> 3) & 1;
    const int xa = arow & 7, xb = brw & 7;

    #pragma unroll 1
    for (int s = 0; s < NIT; s++) {
        const int buf = s % 3;
        MBAR_WAIT(mb + (uint32_t)buf * 8, (s / 3) & 1);
        const uint32_t bA = sb + (uint32_t)buf * STAGEB;
        const uint32_t bB = bA + 16384u;

        #pragma unroll
        for (int ks = 0; ks < 4; ks++) {
            uint32_t afr[4][4], bfr[4][4];
            const int ca = ((2 * ks + achk) ^ xa) * 16;
            const int cb = ((2 * ks + bchk) ^ xb) * 16;
            #pragma unroll
            for (int mt = 0; mt < 4; mt++)
                ldm4(afr[mt], bA + (uint32_t)((wr * 64 + mt * 16 + arow) * 128 + ca));
            #pragma unroll
            for (int n2 = 0; n2 < 4; n2++)
                ldm4(bfr[n2], bB + (uint32_t)((wc * 64 + n2 * 16 + brw) * 128 + cb));
            #pragma unroll
            for (int mt = 0; mt < 4; mt++)
                #pragma unroll
                for (int nt = 0; nt < 8; nt++)
                    mma16816(acc[mt][nt], afr[mt], &bfr[nt >> 1][(nt & 1) * 2]);
        }
        __syncthreads();
        if (s + 3 < NIT) issue(s + 3);
    }

    const int brow = blockIdx.y * 128;
    const int bcol = blockIdx.x * 128;
    const int crow = lane >> 2;
    const int ccol = (lane & 3) * 2;

    if (MODE == 0) {
        #pragma unroll
        for (int nt = 0; nt < 8; nt++) {
            int col = bcol + wc * 64 + nt * 8 + ccol;
            float2 bi = *(const float2*)(bias + col);
            #pragma unroll
            for (int mt = 0; mt < 4; mt++) {
                int row = brow + wr * 64 + mt * 16 + crow;
                float2 v0 = make_float2(acc[mt][nt][0] + bi.x, acc[mt][nt][1] + bi.y);
                float2 v1 = make_float2(acc[mt][nt][2] + bi.x, acc[mt][nt][3] + bi.y);
                *(float2*)(Co + (size_t)row * Ntot + col)       = v0;
                *(float2*)(Co + (size_t)(row + 8) * Ntot + col) = v1;
            }
        }
    } else {
        // write swizzled 16KB attention tiles: [bh][tile][tt][256B, chunk^=(tt&7)]
        const int p  = bcol >> 10;
        __nv_bfloat16* outb = (p == 0) ? Qs : ((p == 1) ? Ks : Vs);
        const float sc = (p == 0) ? 0.125f : 1.f;
        const int hh = ((bcol + wc * 64) >> 6) & 15;
        #pragma unroll
        for (int nt = 0; nt < 8; nt++) {
            int gcol = bcol + wc * 64 + nt * 8 + ccol;
            float2 bi = *(const float2*)(bias + gcol);
            int d = nt * 8 + ccol;
            int o1 = 2 * d;          // hi word byte offset in 256B row
            int o2 = 128 + 2 * d;    // lo word
            #pragma unroll
            for (int mt = 0; mt < 4; mt++) {
                int grow = brow + wr * 64 + mt * 16 + crow;
                #pragma unroll
                for (int half = 0; half < 2; half++) {
                    int m = grow + half * 8;
                    int bb = m >> 11, t = m & 2047;
                    float f0 = (acc[mt][nt][half * 2 + 0] + bi.x) * sc;
                    float f1 = (acc[mt][nt][half * 2 + 1] + bi.y) * sc;
                    __nv_bfloat16 h0 = __float2bfloat16(f0);
                    __nv_bfloat16 l0 = __float2bfloat16(f0 - __bfloat162float(h0));
                    __nv_bfloat16 h1 = __float2bfloat16(f1);
                    __nv_bfloat16 l1 = __float2bfloat16(f1 - __bfloat162float(h1));
                    int tt = t & 63;
                    char* tb = (char*)outb
                        + (((size_t)((bb * H_ + hh) * 32 + (t >> 6))) << 14)
                        + tt * 256;
                    *(uint32_t*)(tb + (((o1 >> 4) ^ (tt & 7)) << 4) + (o1 & 15))
                        = pack_bf2(h0, h1);
                    *(uint32_t*)(tb + (((o2 >> 4) ^ (tt & 7)) << 4) + (o2 & 15))
                        = pack_bf2(l0, l1);
                }
            }
        }
    }
}

// ============================================================================
// HMMA flash attention: bulk-copy staged swizzled 16KB tiles, mbarrier ring.
// smem: Q(16K) | K0 | V0 | K1 | V1 (16K each) | P (64*ASTR) | mbars
// ============================================================================
#define ASTR  272
#define QKV_TILE 16384
#define PS_OFF  (5 * QKV_TILE)
#define AMB_OFF (PS_OFF + 64 * ASTR)
#define ATTN_SMEM (AMB_OFF + 64)    // 99392

__global__ __launch_bounds__(128, 2) void attn_mma(
    const __nv_bfloat16* __restrict__ Qsp, const __nv_bfloat16* __restrict__ Ksp,
    const __nv_bfloat16* __restrict__ Vsp, __nv_bfloat16* __restrict__ Aout)
{
    extern __shared__ char smbuf[];
    const uint32_t sb   = smem_u32(smbuf);
    const uint32_t qs_b = sb;
    const uint32_t ps_b = sb + PS_OFF;
    const uint32_t mb   = sb + AMB_OFF;
    char* Psc = smbuf + PS_OFF;

    const int tid  = threadIdx.x;
    const int lane = tid & 31;
    const int wid  = tid >> 5;
    const int qt   = (int)gridDim.x - 1 - (int)blockIdx.x;
    const int bh   = blockIdx.y;
    const int b = bh >> 4, h = bh & 15;

    const char* Qgc = (const char*)Qsp + ((size_t)(bh * 32 + qt) << 14);
    const char* Kgc = (const char*)Ksp + ((size_t)(bh * 32) << 14);
    const char* Vgc = (const char*)Vsp + ((size_t)(bh * 32) << 14);

    if (tid == 0) { MBAR_INIT(mb + 0, 1); MBAR_INIT(mb + 8, 1); }
    __syncthreads();

    // prologue: Q + K0 + V0 on bar0; K1 + V1 on bar1
    if (tid == 0) {
        MBAR_EXPECT_TX(mb + 0, 3 * QKV_TILE);
        bulk_cp(qs_b, Qgc, QKV_TILE, mb + 0);
        bulk_cp(sb + 1 * QKV_TILE, Kgc, QKV_TILE, mb + 0);
        bulk_cp(sb + 2 * QKV_TILE, Vgc, QKV_TILE, mb + 0);
        if (qt >= 1) {
            MBAR_EXPECT_TX(mb + 8, 2 * QKV_TILE);
            bulk_cp(sb + 3 * QKV_TILE, Kgc + QKV_TILE, QKV_TILE, mb + 8);
            bulk_cp(sb + 4 * QKV_TILE, Vgc + QKV_TILE, QKV_TILE, mb + 8);
        }
    }

    // fragment lane maps
    const int arow = (lane & 7) + ((lane >> 3) & 1) * 8;
    const int achk = lane >> 4;
    const int brw  = (lane & 7) + ((lane >> 4) & 1) * 8;
    const int bchk = (lane >> 3) & 1;
    const int tq = wid * 16 + arow;     // Q token row
    const int xq = tq & 7;
    const int xk = brw & 7;
    const int xv = arow & 7;
    const uint32_t aoffP = (uint32_t)(tq * ASTR + achk * 16);   // P tile (padded)

    float m0 = -1e30f, m1 = -1e30f, l0 = 0.f, l1 = 0.f;
    float accO[8][4];
    #pragma unroll
    for (int nt = 0; nt < 8; nt++)
        #pragma unroll
        for (int q = 0; q < 4; q++) accO[nt][q] = 0.f;

    const int r0 = lane >> 2;
    const int c0 = (lane & 3) * 2;
    const int row0 = wid * 16 + r0;

    #pragma unroll 1
    for (int kt = 0; kt <= qt; kt++) {
        MBAR_WAIT(mb + (uint32_t)(kt & 1) * 8, (kt >> 1) & 1);
        const uint32_t kbuf = sb + (uint32_t)(1 + 2 * (kt & 1)) * QKV_TILE;
        const uint32_t vbuf = kbuf + QKV_TILE;

        // ---- S = Q @ K^T (3-pass: hi*hi, hi*lo, lo*hi)
        float accS[8][4];
        #pragma unroll
        for (int nt = 0; nt < 8; nt++)
            #pragma unroll
            for (int q = 0; q < 4; q++) accS[nt][q] = 0.f;
        #pragma unroll
        for (int pass = 0; pass < 3; pass++) {
            const int aadd = (pass == 2) ? 8 : 0;
            const int badd = (pass == 1) ? 8 : 0;
            #pragma unroll
            for (int ks = 0; ks < 4; ks++) {
                uint32_t afr[4], bfr[4][4];
                ldm4(afr, qs_b + (uint32_t)(tq * 256 +
                     (((2 * ks + achk + aadd) ^ xq) << 4)));
                #pragma unroll
                for (int n2 = 0; n2 < 4; n2++)
                    ldm4(bfr[n2], kbuf + (uint32_t)((n2 * 16 + brw) * 256 +
                         (((2 * ks + bchk + badd) ^ xk) << 4)));
                #pragma unroll
                for (int nt = 0; nt < 8; nt++)
                    mma16816(accS[nt], afr, &bfr[nt >> 1][(nt & 1) * 2]);
            }
        }

        if (kt == qt) {
            #pragma unroll
            for (int nt = 0; nt < 8; nt++) {
                int col = nt * 8 + c0;
                if (col     > row0)     accS[nt][0] = -1e30f;
                if (col + 1 > row0)     accS[nt][1] = -1e30f;
                if (col     > row0 + 8) accS[nt][2] = -1e30f;
                if (col + 1 > row0 + 8) accS[nt][3] = -1e30f;
            }
        }

        // ---- online softmax + write P (hi/lo into padded Ps)
        {
            float mx0 = -1e30f, mx1 = -1e30f;
            #pragma unroll
            for (int nt = 0; nt < 8; nt++) {
                mx0 = fmaxf(mx0, fmaxf(accS[nt][0], accS[nt][1]));
                mx1 = fmaxf(mx1, fmaxf(accS[nt][2], accS[nt][3]));
            }
            mx0 = fmaxf(mx0, __shfl_xor_sync(0xffffffffu, mx0, 1));
            mx0 = fmaxf(mx0, __shfl_xor_sync(0xffffffffu, mx0, 2));
            mx1 = fmaxf(mx1, __shfl_xor_sync(0xffffffffu, mx1, 1));
            mx1 = fmaxf(mx1, __shfl_xor_sync(0xffffffffu, mx1, 2));

            float mn0 = fmaxf(m0, mx0), mn1 = fmaxf(m1, mx1);
            float al0 = __expf(m0 - mn0), al1 = __expf(m1 - mn1);
            m0 = mn0; m1 = mn1;

            char* prow0 = Psc + (wid * 16 + r0) * ASTR + c0 * 2;
            char* prow1 = prow0 + 8 * ASTR;
            float sum0 = 0.f, sum1 = 0.f;
            #pragma unroll
            for (int nt = 0; nt < 8; nt++) {
                float p0 = __expf(accS[nt][0] - mn0);
                float p1 = __expf(accS[nt][1] - mn0);
                float p2 = __expf(accS[nt][2] - mn1);
                float p3 = __expf(accS[nt][3] - mn1);
                sum0 += p0 + p1; sum1 += p2 + p3;
                __nv_bfloat16 h0 = __float2bfloat16(p0), h1 = __float2bfloat16(p1);
                __nv_bfloat16 h2 = __float2bfloat16(p2), h3 = __float2bfloat16(p3);
                __nv_bfloat16 g0 = __float2bfloat16(p0 - __bfloat162float(h0));
                __nv_bfloat16 g1 = __float2bfloat16(p1 - __bfloat162float(h1));
                __nv_bfloat16 g2 = __float2bfloat16(p2 - __bfloat162float(h2));
                __nv_bfloat16 g3 = __float2bfloat16(p3 - __bfloat162float(h3));
                *(uint32_t*)(prow0 + nt * 16)        = pack_bf2(h0, h1);
                *(uint32_t*)(prow0 + 128 + nt * 16)  = pack_bf2(g0, g1);
                *(uint32_t*)(prow1 + nt * 16)        = pack_bf2(h2, h3);
                *(uint32_t*)(prow1 + 128 + nt * 16)  = pack_bf2(g2, g3);
            }
            sum0 += __shfl_xor_sync(0xffffffffu, sum0, 1);
            sum0 += __shfl_xor_sync(0xffffffffu, sum0, 2);
            sum1 += __shfl_xor_sync(0xffffffffu, sum1, 1);
            sum1 += __shfl_xor_sync(0xffffffffu, sum1, 2);
            l0 = l0 * al0 + sum0;
            l1 = l1 * al1 + sum1;

            #pragma unroll
            for (int nt = 0; nt < 8; nt++) {
                accO[nt][0] *= al0; accO[nt][1] *= al0;
                accO[nt][2] *= al1; accO[nt][3] *= al1;
            }
        }
        __syncwarp();

        // ---- O += P @ V (3-pass; V via ldmatrix.trans, swizzled tile)
        #pragma unroll
        for (int pass = 0; pass < 3; pass++) {
            const uint32_t aadd = (pass == 2) ? 128u : 0u;   // P lo
            const int badd = (pass == 1) ? 8 : 0;            // V lo
            #pragma unroll
            for (int ks = 0; ks < 4; ks++) {
                uint32_t pfr[4], vfr[4][4];
                ldm4(pfr, ps_b + aoffP + aadd + ks * 32);
                #pragma unroll
                for (int n2 = 0; n2 < 4; n2++)
                    ldm4t(vfr[n2], vbuf + (uint32_t)((ks * 16 + arow) * 256 +
                          (((n2 * 2 + achk + badd) ^ xv) << 4)));
                #pragma unroll
                for (int nt = 0; nt < 8; nt++)
                    mma16816(accO[nt], pfr, &vfr[nt >> 1][(nt & 1) * 2]);
            }
        }

        __syncthreads();   // all warps done with this buffer + P
        if (tid == 0 && kt + 2 <= qt) {
            uint32_t mbar = mb + (uint32_t)(kt & 1) * 8;
            uint32_t nb = sb + (uint32_t)(1 + 2 * (kt & 1)) * QKV_TILE;
            MBAR_EXPECT_TX(mbar, 2 * QKV_TILE);
            bulk_cp(nb,            Kgc + ((size_t)(kt + 2) << 14), QKV_TILE, mbar);
            bulk_cp(nb + QKV_TILE, Vgc + ((size_t)(kt + 2) << 14), QKV_TILE, mbar);
        }
    }

    // ---- normalize + write [hi,hi,lo] triplets into TILED-SWIZZLED gA
    float inv0 = 1.f / l0, inv1 = 1.f / l1;
    int grow = qt * 64 + wid * 16 + r0;
    size_t m0r = (size_t)b * T_ + grow;
    size_t m1r = m0r + 8;
    char* Ac = (char*)Aout;
    auto writeWord = [&](size_t m, int o, uint32_t val) {
        int gc = o >> 4, st = gc >> 3, pc = (gc & 7) ^ ((int)m & 7);
        *(uint32_t*)(Ac + (((m >> 7) * NIT + st) << 14)
                        + (m & 127) * 128 + pc * 16 + (o & 15)) = val;
    };
    #pragma unroll
    for (int nt = 0; nt < 8; nt++) {
        int d = nt * 8 + c0;
        int o = (h * D_ + d) * 6;
        float f0 = accO[nt][0] * inv0, f1 = accO[nt][1] * inv0;
        float f2 = accO[nt][2] * inv1, f3 = accO[nt][3] * inv1;
        __nv_bfloat16 h0 = __float2bfloat16(f0);
        __nv_bfloat16 e0 = __float2bfloat16(f0 - __bfloat162float(h0));
        __nv_bfloat16 h1 = __float2bfloat16(f1);
        __nv_bfloat16 e1 = __float2bfloat16(f1 - __bfloat162float(h1));
        __nv_bfloat16 h2 = __float2bfloat16(f2);
        __nv_bfloat16 e2 = __float2bfloat16(f2 - __bfloat162float(h2));
        __nv_bfloat16 h3 = __float2bfloat16(f3);
        __nv_bfloat16 e3 = __float2bfloat16(f3 - __bfloat162float(h3));
        writeWord(m0r, o + 0, pack_bf2(h0, h0));
        writeWord(m0r, o + 4, pack_bf2(e0, h1));
        writeWord(m0r, o + 8, pack_bf2(h1, e1));
        writeWord(m1r, o + 0, pack_bf2(h2, h2));
        writeWord(m1r, o + 4, pack_bf2(e2, h3));
        writeWord(m1r, o + 8, pack_bf2(h3, e3));
    }
}

// ---------------------------------------------------------------------------
extern "C" void kernel_launch(void* const* d_in, const int* in_sizes, int n_in,
                              void* d_out, int out_size)
{
    const float* x     = (const float*)d_in[0];
    const float* Wqkv  = (const float*)d_in[1];
    const float* bqkv  = (const float*)d_in[2];
    const float* Wproj = (const float*)d_in[3];
    const float* bproj = (const float*)d_in[4];
    float* out = (float*)d_out;

    __nv_bfloat16 *gA_p = nullptr, *gBq_p = nullptr, *gBp_p = nullptr;
    __nv_bfloat16 *q_p = nullptr, *k_p = nullptr, *v_p = nullptr;
    cudaGetSymbolAddress((void**)&gA_p,  gA);
    cudaGetSymbolAddress((void**)&gBq_p, gBq);
    cudaGetSymbolAddress((void**)&gBp_p, gBp);
    cudaGetSymbolAddress((void**)&q_p,   gQsp);
    cudaGetSymbolAddress((void**)&k_p,   gKsp);
    cudaGetSymbolAddress((void**)&v_p,   gVsp);

    cudaFuncSetAttribute(attn_mma,
                         cudaFuncAttributeMaxDynamicSharedMemorySize, ATTN_SMEM);
    cudaFuncSetAttribute(gemm_tc<0>,
                         cudaFuncAttributeMaxDynamicSharedMemorySize, GSMEM);
    cudaFuncSetAttribute(gemm_tc<1>,
                         cudaFuncAttributeMaxDynamicSharedMemorySize, GSMEM);

    // conversions (tiled+swizzled outputs)
    convert_w<<<dim3(QKVN / 32, C_ / 32), 128>>>(Wqkv, gBq_p, QKVN);
    convert_w<<<dim3(C_ / 32, C_ / 32), 128>>>(Wproj, gBp_p, C_);
    convert_act<<<(M_ * C_ / 8) / 256, 256>>>(x, gA_p);

    // 1) QKV projection, fused swizzled-tile q/k/v epilogue
    gemm_tc<1><<<dim3(QKVN / 128, M_ / 128), 128, GSMEM>>>(
        gA_p, gBq_p, bqkv, nullptr, QKVN, q_p, k_p, v_p);

    // 2) causal flash attention; epilogue writes proj-input triplets into gA
    attn_mma<<<dim3(T_ / 64, B_ * H_), 128, ATTN_SMEM>>>(q_p, k_p, v_p, gA_p);

    // 3) output projection
    gemm_tc<0><<<dim3(C_ / 128, M_ / 128), 128, GSMEM>>>(
        gA_p, gBp_p, bproj, out, C_, nullptr, nullptr, nullptr);
}